// round 14
// baseline (speedup 1.0000x reference)
#include <cuda_runtime.h>
#include <cuda_fp16.h>
#include <math.h>
#include <stdint.h>

#define H 512
#define F 1024
#define E 16
#define MAX_T 8192
#define EPS 1e-5f

// Per-compile-pass feature detection: tcgen05 only legal on sm_103a-style targets.
#if defined(__CUDA_ARCH__) && (defined(__CUDA_ARCH_FEAT_SM103_ALL) || \
    defined(__CUDA_ARCH_FEAT_SM100_ALL) || defined(__CUDA_ARCH_SPECIFIC__) || \
    defined(__CUDA_ARCH_FAMILY_SPECIFIC__))
#define USE_TC 1
#else
#define USE_TC 0
#endif

// ---------------------------------------------------------------------------
// Scratch (no allocation allowed -> device globals)
// ---------------------------------------------------------------------------
__device__ __align__(128) __half g_x[(size_t)MAX_T * H];
__device__ __align__(128) __half g_w1t[(size_t)E * F * H];   // [e][f][h]
__device__ __align__(128) __half g_w2t[(size_t)E * H * F];   // [e][h][f]
__device__ float g_b1part[8][E * F];
__device__ __align__(128) __half g_h[(size_t)E * MAX_T * F]; // [e][t][f]

// Self-resetting counters (proven R10-R13): low16 = producers, high16 = consumers;
// last consumer zeroes the word. Zero-init at load; invariant across replays.
__device__ unsigned g_cH[(MAX_T / 128) * E];   // prod 8, cons 4
__device__ unsigned g_cLN[MAX_T / 128];        // prod 8, cons 128

// ---------------------------------------------------------------------------
// Common helpers
// ---------------------------------------------------------------------------
__device__ __forceinline__ uint32_t smem_to_u32(const void* p) {
    uint32_t a;
    asm("{ .reg .u64 t; cvta.to.shared.u64 t, %1; cvt.u32.u64 %0, t; }" : "=r"(a) : "l"(p));
    return a;
}
#define SMEM_SWIZZLE_128B(o) ((o) ^ (((o) >> 3) & 0x70))

__device__ __forceinline__ void cpa16(uint32_t dst, const void* src) {
    asm volatile("cp.async.cg.shared.global [%0], [%1], 16;" :: "r"(dst), "l"(src));
}
#define CP_COMMIT() asm volatile("cp.async.commit_group;" ::: "memory")
__device__ __forceinline__ void cp_wait1() { asm volatile("cp.async.wait_group 1;" ::: "memory"); }
__device__ __forceinline__ void cp_wait0() { asm volatile("cp.async.wait_group 0;" ::: "memory"); }

__device__ __forceinline__ float gelu_erf(float x) {
    return 0.5f * x * (1.0f + erff(x * 0.70710678118654752f));
}

// Counter ops
__device__ __forceinline__ void ctr_release(unsigned* c) {
    asm volatile("red.release.gpu.global.add.u32 [%0], 1;" :: "l"(c) : "memory");
}
__device__ __forceinline__ unsigned ld_acq(const unsigned* c) {
    unsigned v;
    asm volatile("ld.acquire.gpu.global.u32 %0, [%1];" : "=r"(v) : "l"(c) : "memory");
    return v;
}
__device__ __forceinline__ void ctr_wait_consume(unsigned* c, unsigned target, unsigned ncons) {
    unsigned v;
    do {
        v = ld_acq(c);
        if ((v & 0xFFFFu) >= target) break;
        __nanosleep(256);
    } while (true);
    unsigned old = atomicAdd(c, 1u << 16);
    if ((old >> 16) == ncons - 1) atomicExch(c, 0u);
}

// Tile geometry: M=128 tokens, N=128, K-step=64
// SMEM stage: A(16K) B(16K) = 32KB; 2 stages = 64KB; 3 CTAs/SM
#define OFF_B 16384
#define STAGE_BYTES 32768
#define S_CTRL 65536             // tmem ptr (tc path)
#define S_MBAR 65552
#define S_B1   65568             // 128 floats of b1' for this fc tile
#define SMEM_BYTES 66080

// Full-stage load (A + B halves)
__device__ __forceinline__ void stage_load_async(uint32_t sbase,
    const __half* __restrict__ A, size_t as,
    const __half* __restrict__ B, size_t bs,
    int k0, int tid)
{
    #pragma unroll
    for (int it = 0; it < 4; it++) {
        int v = tid + it * 256;
        int r = v >> 3, c = v & 7;
        uint32_t off = SMEM_SWIZZLE_128B((uint32_t)(r * 128 + c * 16));
        cpa16(sbase + off,         A + (size_t)r * as + k0 + c * 8);
        cpa16(sbase + OFF_B + off, B + (size_t)r * bs + k0 + c * 8);
    }
}

// ===========================================================================
#if USE_TC
// tcgen05 path: one M=128 x N=128 MMA region (2-stage pipeline)
// ===========================================================================
__device__ __forceinline__ uint32_t elect_one_pred() {
    uint32_t pred;
    asm volatile("{\n\t.reg .pred p;\n\telect.sync _|p, 0xFFFFFFFF;\n\t"
                 "selp.b32 %0, 1, 0, p;\n\t}" : "=r"(pred));
    return pred;
}
static constexpr uint64_t SMEM_DESC_BASE_SW128 =
    (uint64_t(2) << 61) | (uint64_t(1) << 46) | (uint64_t(64) << 32) | (uint64_t(1) << 16);
#define MAKE_SMEM_DESC(a) (SMEM_DESC_BASE_SW128 | ((uint64_t)((a) >> 4) & 0x3FFF))

#define TCGEN05_ALLOC(sr, n) \
    asm volatile("tcgen05.alloc.cta_group::1.sync.aligned.shared::cta.b32 [%0], %1;" \
                 :: "r"((uint32_t)(sr)), "r"((uint32_t)(n)) : "memory")
#define TCGEN05_DEALLOC(t, n) \
    asm volatile("tcgen05.dealloc.cta_group::1.sync.aligned.b32 %0, %1;" :: "r"(t), "r"(n))
#define TCGEN05_RELINQUISH() \
    asm volatile("tcgen05.relinquish_alloc_permit.cta_group::1.sync.aligned;")
#define TCGEN05_COMMIT(m) \
    asm volatile("tcgen05.commit.cta_group::1.mbarrier::arrive::one.shared::cluster.b64 [%0];" \
                 :: "r"((uint32_t)(m)) : "memory")
#define TCGEN05_FENCE_AFTER() asm volatile("tcgen05.fence::after_thread_sync;" ::: "memory")
#define TCGEN05_WAIT_LD() asm volatile("tcgen05.wait::ld.sync.aligned;" ::: "memory")
#define MBARRIER_INIT(m, c) \
    asm volatile("mbarrier.init.shared.b64 [%0], %1;" :: "r"((uint32_t)(m)), "r"((uint32_t)(c)) : "memory")
#define MBARRIER_INVAL(m) \
    asm volatile("mbarrier.inval.shared.b64 [%0];" :: "r"((uint32_t)(m)) : "memory")

#define MBARRIER_WAIT_PARITY(mb, ph) do {                                         \
    uint32_t _m = (uint32_t)(mb), _p = (uint32_t)(ph), _d;                         \
    asm volatile("{\n\t.reg .pred p;\n\t"                                          \
        "mbarrier.try_wait.parity.acquire.cta.shared::cta.b64 p, [%1], %2;\n\t"    \
        "selp.b32 %0, 1, 0, p;\n\t}" : "=r"(_d) : "r"(_m), "r"(_p) : "memory");    \
    if (!_d) {                                                                     \
        asm volatile("{\n\t.reg .pred P1;\n\t"                                     \
            "WL_%=:\n\t"                                                           \
            "mbarrier.try_wait.parity.acquire.cta.shared::cta.b64 P1, [%0], %1, 0x989680;\n\t" \
            "@P1 bra.uni WD_%=;\n\t"                                               \
            "bra.uni WL_%=;\n\t"                                                   \
            "WD_%=:\n\t}" :: "r"(_m), "r"(_p) : "memory");                         \
    }                                                                              \
} while (0)

#define TCGEN05_LD_X32(r, a)                                                       \
    asm volatile("tcgen05.ld.sync.aligned.32x32b.x32.b32 "                         \
        "{%0, %1, %2, %3, %4, %5, %6, %7, %8, %9, %10, %11, %12, %13, %14, %15, "  \
        " %16, %17, %18, %19, %20, %21, %22, %23, %24, %25, %26, %27, %28, %29, %30, %31}, [%32];" \
        : "=r"((r)[0]), "=r"((r)[1]), "=r"((r)[2]), "=r"((r)[3]),                  \
          "=r"((r)[4]), "=r"((r)[5]), "=r"((r)[6]), "=r"((r)[7]),                  \
          "=r"((r)[8]), "=r"((r)[9]), "=r"((r)[10]), "=r"((r)[11]),                \
          "=r"((r)[12]), "=r"((r)[13]), "=r"((r)[14]), "=r"((r)[15]),              \
          "=r"((r)[16]), "=r"((r)[17]), "=r"((r)[18]), "=r"((r)[19]),              \
          "=r"((r)[20]), "=r"((r)[21]), "=r"((r)[22]), "=r"((r)[23]),              \
          "=r"((r)[24]), "=r"((r)[25]), "=r"((r)[26]), "=r"((r)[27]),              \
          "=r"((r)[28]), "=r"((r)[29]), "=r"((r)[30]), "=r"((r)[31])               \
        : "r"(a))

__device__ __forceinline__ void mma_f16_ss(uint32_t d_tmem, uint64_t a_desc,
                                           uint64_t b_desc, uint32_t idesc, bool acc) {
    uint32_t en = acc ? 1u : 0u;
    asm volatile("{\n\t.reg .pred p;\n\tsetp.ne.u32 p, %4, 0;\n\t"
                 "tcgen05.mma.cta_group::1.kind::f16 [%0], %1, %2, %3, p;\n\t}"
                 :: "r"(d_tmem), "l"(a_desc), "l"(b_desc), "r"(idesc), "r"(en)
                 : "memory");
}
#define MMA_IDESC ((1u << 4) | ((128u / 8u) << 17) | ((128u / 16u) << 24))

__device__ __forceinline__ uint32_t tc_prologue(uint32_t su, int tid, int wid) {
    if (wid == 0) TCGEN05_ALLOC(su + S_CTRL, 128);
    if (tid == 128) MBARRIER_INIT(su + S_MBAR, 1);
    __syncthreads();
    uint32_t tmem;
    asm volatile("ld.shared.b32 %0, [%1];" : "=r"(tmem) : "r"(su + S_CTRL));
    if (wid == 0) TCGEN05_RELINQUISH();
    __syncthreads();
    return tmem;
}

__device__ __forceinline__ void tc_mainloop(uint32_t su, uint32_t tmem,
    const __half* __restrict__ A, size_t as,
    const __half* __restrict__ B, size_t bs,
    int K, int tid, int wid)
{
    const int nk = K / 64;
    stage_load_async(su, A, as, B, bs, 0, tid);
    CP_COMMIT();
    for (int ks = 0; ks < nk; ks++) {
        if (ks > 0) MBARRIER_WAIT_PARITY(su + S_MBAR, (ks - 1) & 1);
        if (ks + 1 < nk) {
            stage_load_async(su + ((ks + 1) & 1) * STAGE_BYTES,
                             A, as, B, bs, (ks + 1) * 64, tid);
            CP_COMMIT();
            cp_wait1();
        } else {
            cp_wait0();
        }
        __syncthreads();
        if (wid == 0 && elect_one_pred()) {
            asm volatile("fence.proxy.async.shared::cta;" ::: "memory");
            uint32_t sb = su + (ks & 1) * STAGE_BYTES;
            uint64_t dA = MAKE_SMEM_DESC(sb);
            uint64_t dB = MAKE_SMEM_DESC(sb + OFF_B);
            #pragma unroll
            for (int kk = 0; kk < 4; kk++) {
                bool acc0 = (ks > 0) || (kk > 0);
                mma_f16_ss(tmem, dA + kk * 2, dB + kk * 2, MMA_IDESC, acc0);
            }
            TCGEN05_COMMIT(su + S_MBAR);
        }
        __syncthreads();
    }
    MBARRIER_WAIT_PARITY(su + S_MBAR, (nk - 1) & 1);
    TCGEN05_FENCE_AFTER();
}

__device__ __forceinline__ void tc_release_tm(uint32_t su, uint32_t tmem, int tid, int wid) {
    __syncthreads();
    if (tid == 128) MBARRIER_INVAL(su + S_MBAR);
    __syncthreads();
    if (wid == 0) TCGEN05_DEALLOC(tmem, 128);
}
#endif  // USE_TC

// ===========================================================================
#if !USE_TC
// mma.sync fallback: 8 warps, warp tile 32x64, 2-stage pipeline
// ===========================================================================
__device__ __forceinline__ void ldsm_x4(uint32_t* r, uint32_t a) {
    asm volatile("ldmatrix.sync.aligned.m8n8.x4.shared.b16 {%0,%1,%2,%3}, [%4];"
                 : "=r"(r[0]), "=r"(r[1]), "=r"(r[2]), "=r"(r[3]) : "r"(a));
}
__device__ __forceinline__ void mma16816(float* d, const uint32_t* a, const uint32_t* b) {
    asm volatile("mma.sync.aligned.m16n8k16.row.col.f32.f16.f16.f32 "
                 "{%0,%1,%2,%3}, {%4,%5,%6,%7}, {%8,%9}, {%0,%1,%2,%3};"
                 : "+f"(d[0]), "+f"(d[1]), "+f"(d[2]), "+f"(d[3])
                 : "r"(a[0]), "r"(a[1]), "r"(a[2]), "r"(a[3]), "r"(b[0]), "r"(b[1]));
}

__device__ __forceinline__ void mmasync_mainloop(uint32_t su,
    const __half* __restrict__ A, size_t as,
    const __half* __restrict__ B, size_t bs,
    int K, int tid, float acc[2][8][4])
{
    const int nk = K / 64;
    const int wid = tid >> 5, lane = tid & 31;
    const int wm = wid >> 1, wn = wid & 1;

    stage_load_async(su, A, as, B, bs, 0, tid);
    CP_COMMIT();

    for (int ks = 0; ks < nk; ks++) {
        if (ks + 1 < nk) {
            stage_load_async(su + ((ks + 1) & 1) * STAGE_BYTES,
                             A, as, B, bs, (ks + 1) * 64, tid);
            CP_COMMIT();
            cp_wait1();
        } else {
            cp_wait0();
        }
        __syncthreads();

        uint32_t sA = su + (ks & 1) * STAGE_BYTES;
        uint32_t sB = sA + OFF_B;

        #pragma unroll
        for (int k16 = 0; k16 < 64; k16 += 16) {
            uint32_t bh[8][2];
            #pragma unroll
            for (int jj = 0; jj < 4; jj++) {
                int n = wn * 64 + jj * 16 + (lane & 7) + ((lane >> 3) & 1) * 8;
                int k = k16 + (lane >> 4) * 8;
                uint32_t addr = sB + SMEM_SWIZZLE_128B((uint32_t)(n * 128 + k * 2));
                uint32_t t[4];
                ldsm_x4(t, addr);
                bh[2 * jj][0] = t[0]; bh[2 * jj + 1][0] = t[1];
                bh[2 * jj][1] = t[2]; bh[2 * jj + 1][1] = t[3];
            }
            #pragma unroll
            for (int i = 0; i < 2; i++) {
                int m = wm * 32 + i * 16 + (lane & 15);
                int k = k16 + (lane >> 4) * 8;
                uint32_t addr = sA + SMEM_SWIZZLE_128B((uint32_t)(m * 128 + k * 2));
                uint32_t ah[4];
                ldsm_x4(ah, addr);
                #pragma unroll
                for (int j = 0; j < 8; j++)
                    mma16816(acc[i][j], ah, bh[j]);
            }
        }
        __syncthreads();
    }
}
#endif  // !USE_TC

// ---------------------------------------------------------------------------
// Prep kernel (high occupancy): W1^T*g + b1 partials + W2^T only (LN moved
// into the GEMM kernel where it overlaps GEMM1's wave ramp).
// ---------------------------------------------------------------------------
__global__ void __launch_bounds__(256) prep_kernel(
    const float* __restrict__ ln_g, const float* __restrict__ ln_b,
    const float* __restrict__ W1,   const float* __restrict__ W2)
{
    __shared__ float ts[64][65];
    __shared__ float ps[4][64];
    const int tid = threadIdx.x;
    int b = blockIdx.x;

    if (b < 2048) {
        // ---- W1^T * g + b1 partials ----
        int f0 = (b & 15) * 64, h0 = ((b >> 4) & 7) * 64, e = b >> 7;
        #pragma unroll
        for (int i = 0; i < 16; i++) {
            int idx = tid + i * 256, r = idx >> 6, c = idx & 63;
            ts[r][c] = W1[((size_t)e * H + h0 + r) * F + f0 + c];
        }
        __syncthreads();
        #pragma unroll
        for (int i = 0; i < 16; i++) {
            int idx = tid + i * 256, r = idx >> 6, c = idx & 63;
            float w = ts[c][r] * ln_g[e * H + h0 + c];
            g_w1t[((size_t)e * F + f0 + r) * H + h0 + c] = __float2half_rn(w);
        }
        {
            int f = tid & 63, q = tid >> 6;
            const float* lb = ln_b + e * H + h0 + q * 16;
            float s = 0.0f;
            #pragma unroll
            for (int r = 0; r < 16; r++) s += lb[r] * ts[q * 16 + r][f];
            ps[q][f] = s;
        }
        __syncthreads();
        if (tid < 64) {
            float a = ps[0][tid] + ps[1][tid] + ps[2][tid] + ps[3][tid];
            g_b1part[h0 >> 6][e * F + f0 + tid] = a;
        }
        return;
    }
    b -= 2048;

    // ---- W2^T ----
    {
        int h0 = (b & 7) * 64, f0 = ((b >> 3) & 15) * 64, e = b >> 7;
        #pragma unroll
        for (int i = 0; i < 16; i++) {
            int idx = tid + i * 256, r = idx >> 6, c = idx & 63;
            ts[r][c] = W2[((size_t)e * F + f0 + r) * H + h0 + c];
        }
        __syncthreads();
        #pragma unroll
        for (int i = 0; i < 16; i++) {
            int idx = tid + i * 256, r = idx >> 6, c = idx & 63;
            g_w2t[((size_t)e * H + h0 + r) * F + f0 + c] = __float2half_rn(ts[c][r]);
        }
    }
}

// ---------------------------------------------------------------------------
// Fused GEMM kernel: [GEMM1 nb1][GEMM2 nb2], 3 CTAs/SM, 2-stage pipeline.
// GEMM1 CTAs with e==0 also compute the LN shard for their (tile, fc) rows;
// all 128 GEMM1 CTAs of a tile wait on g_cLN[t] (overlaps with wave ramp).
// ---------------------------------------------------------------------------
__global__ void __launch_bounds__(256, 3) gemm_fused_kernel(
    const float* __restrict__ tokens, const float* __restrict__ b1,
    const float* __restrict__ b2, float* __restrict__ out, int tiles)
{
    extern __shared__ char smem[];
    uint32_t su = smem_to_u32(smem);
    const int tid = threadIdx.x, wid = tid >> 5, lane = tid & 31;
    const int nb1 = tiles * E * 8;
    int b = blockIdx.x;

    if (b < nb1) {
        // ================= GEMM1 producer =================
        const int t = b >> 7;
        const int e = (b >> 3) & 15;
        const int fi = b & 7;
        const int fc = fi * 128;
        const int tok0 = t * 128;
        float* sm_b1 = reinterpret_cast<float*>(smem + S_B1);

        // ---- LN shard: e==0 CTAs normalize rows [tok0+fi*16, +16) ----
        if (e == 0) {
            #pragma unroll
            for (int rr = 0; rr < 2; rr++) {
                int row = tok0 + fi * 16 + wid * 2 + rr;
                const float* x = tokens + (size_t)row * H;
                float v[16];
                float s = 0.0f;
                #pragma unroll
                for (int i = 0; i < 16; i++) { v[i] = x[lane + 32 * i]; s += v[i]; }
                #pragma unroll
                for (int o = 16; o > 0; o >>= 1) s += __shfl_xor_sync(0xffffffffu, s, o);
                float mu = s * (1.0f / H);
                float q = 0.0f;
                #pragma unroll
                for (int i = 0; i < 16; i++) { v[i] -= mu; q += v[i] * v[i]; }
                #pragma unroll
                for (int o = 16; o > 0; o >>= 1) q += __shfl_xor_sync(0xffffffffu, q, o);
                float rs = rsqrtf(q * (1.0f / H) + EPS);
                __half* ox = g_x + (size_t)row * H;
                #pragma unroll
                for (int i = 0; i < 16; i++)
                    ox[lane + 32 * i] = __float2half_rn(v[i] * rs);
            }
            __threadfence();
            __syncthreads();
            if (tid == 0) ctr_release(&g_cLN[t]);
        }

        // b1' reduction (independent of LN)
        if (tid < 128) {
            int fg = e * F + fc + tid;
            float a = b1[fg];
            #pragma unroll
            for (int s = 0; s < 8; s++) a += g_b1part[s][fg];
            sm_b1[tid] = a;
        }

        // Wait for all 8 LN shards of this tile
        if (tid == 0) ctr_wait_consume(&g_cLN[t], 8u, 128u);
        __syncthreads();
        __threadfence();

        const __half* A = g_x + (size_t)tok0 * H;
        const __half* B = g_w1t + ((size_t)e * F + fc) * H;

#if USE_TC
        uint32_t tmem = tc_prologue(su, tid, wid);
        tc_mainloop(su, tmem, A, H, B, H, H, tid, wid);
        const int row = (wid & 3) * 32 + lane;
        const int ch = (wid >> 2) * 64;
        const size_t hrow = ((size_t)e * MAX_T + tok0 + row) * F;
        for (int cb = 0; cb < 64; cb += 32) {
            uint32_t r[32];
            TCGEN05_LD_X32(r, tmem + ch + cb);
            TCGEN05_WAIT_LD();
            int fglob = fc + ch + cb;
            __half h8[8];
            #pragma unroll
            for (int j = 0; j < 32; j++) {
                float v = __uint_as_float(r[j]) + sm_b1[ch + cb + j];
                h8[j & 7] = __float2half_rn(gelu_erf(v));
                if ((j & 7) == 7)
                    *reinterpret_cast<uint4*>(&g_h[hrow + fglob + (j & ~7)]) =
                        *reinterpret_cast<uint4*>(h8);
            }
        }
        tc_release_tm(su, tmem, tid, wid);
#else
        float acc[2][8][4];
        #pragma unroll
        for (int i = 0; i < 2; i++)
            #pragma unroll
            for (int j = 0; j < 8; j++)
                #pragma unroll
                for (int q = 0; q < 4; q++) acc[i][j][q] = 0.0f;

        mmasync_mainloop(su, A, H, B, H, H, tid, acc);

        const int wm = wid >> 1, wn = wid & 1;
        #pragma unroll
        for (int i = 0; i < 2; i++) {
            #pragma unroll
            for (int j = 0; j < 8; j++) {
                int fl = wn * 64 + j * 8 + (lane & 3) * 2;
                int r0 = tok0 + wm * 32 + i * 16 + (lane >> 2);
                float bb0 = sm_b1[fl], bb1 = sm_b1[fl + 1];
                #pragma unroll
                for (int half = 0; half < 2; half++) {
                    int rr = r0 + half * 8;
                    float v0 = acc[i][j][2 * half + 0] + bb0;
                    float v1 = acc[i][j][2 * half + 1] + bb1;
                    __half h0 = __float2half_rn(gelu_erf(v0));
                    __half h1 = __float2half_rn(gelu_erf(v1));
                    uint32_t ph = ((uint32_t)__half_as_ushort(h1) << 16) | __half_as_ushort(h0);
                    *reinterpret_cast<uint32_t*>(&g_h[((size_t)e * MAX_T + rr) * F + fc + fl]) = ph;
                }
            }
        }
#endif
        __threadfence();
        __syncthreads();
        if (tid == 0) ctr_release(&g_cH[t * E + e]);
        return;
    }
    b -= nb1;

    // ================= GEMM2 consumer =================
    {
        const int t = b >> 6;
        const int e = (b >> 2) & 15;
        const int hh0 = (b & 3) * 128;
        const int tok0 = t * 128;

        if (tid == 0) ctr_wait_consume(&g_cH[t * E + e], 8u, 4u);
        __syncthreads();
        __threadfence();

        const __half* A = g_h + ((size_t)e * MAX_T + tok0) * F;
        const __half* B = g_w2t + ((size_t)e * H + hh0) * F;

#if USE_TC
        uint32_t tmem = tc_prologue(su, tid, wid);
        tc_mainloop(su, tmem, A, F, B, F, F, tid, wid);
        const int row = (wid & 3) * 32 + lane;
        const int ch = (wid >> 2) * 64;
        float* orow = out + (((size_t)(tok0 + row)) * E + e) * H;
        for (int cb = 0; cb < 64; cb += 32) {
            uint32_t r[32];
            TCGEN05_LD_X32(r, tmem + ch + cb);
            TCGEN05_WAIT_LD();
            int hglob = hh0 + ch + cb;
            float v4[4];
            #pragma unroll
            for (int j = 0; j < 32; j++) {
                v4[j & 3] = __uint_as_float(r[j]) + b2[e * H + hglob + j];
                if ((j & 3) == 3)
                    *reinterpret_cast<uint4*>(orow + hglob + (j & ~3)) =
                        *reinterpret_cast<uint4*>(v4);
            }
        }
        tc_release_tm(su, tmem, tid, wid);
#else
        float acc[2][8][4];
        #pragma unroll
        for (int i = 0; i < 2; i++)
            #pragma unroll
            for (int j = 0; j < 8; j++)
                #pragma unroll
                for (int q = 0; q < 4; q++) acc[i][j][q] = 0.0f;

        mmasync_mainloop(su, A, F, B, F, F, tid, acc);

        const int wm = wid >> 1, wn = wid & 1;
        const float* b2p = b2 + e * H;
        #pragma unroll
        for (int i = 0; i < 2; i++) {
            #pragma unroll
            for (int j = 0; j < 8; j++) {
                int hj = hh0 + wn * 64 + j * 8 + (lane & 3) * 2;
                int r0 = tok0 + wm * 32 + i * 16 + (lane >> 2);
                float bb0 = b2p[hj], bb1 = b2p[hj + 1];
                #pragma unroll
                for (int half = 0; half < 2; half++) {
                    int rr = r0 + half * 8;
                    float2 v = make_float2(acc[i][j][2 * half + 0] + bb0,
                                           acc[i][j][2 * half + 1] + bb1);
                    *reinterpret_cast<float2*>(out + ((size_t)rr * E + e) * H + hj) = v;
                }
            }
        }
#endif
    }
}

// ---------------------------------------------------------------------------
extern "C" void kernel_launch(void* const* d_in, const int* in_sizes, int n_in,
                              void* d_out, int out_size)
{
    const float* tokens = (const float*)d_in[0];
    const float* ln_g   = (const float*)d_in[1];
    const float* ln_b   = (const float*)d_in[2];
    const float* W1     = (const float*)d_in[3];
    const float* b1     = (const float*)d_in[4];
    const float* W2     = (const float*)d_in[5];
    const float* b2     = (const float*)d_in[6];
    float* out = (float*)d_out;

    int T = in_sizes[0] / H;      // 8192
    int tiles = T / 128;          // 64

    cudaFuncSetAttribute(gemm_fused_kernel, cudaFuncAttributeMaxDynamicSharedMemorySize, SMEM_BYTES);

    prep_kernel<<<4096, 256>>>(ln_g, ln_b, W1, W2);

    int ng = tiles * E * 8 + tiles * E * 4;   // 12288
    gemm_fused_kernel<<<ng, 256, SMEM_BYTES>>>(tokens, b1, b2, out, tiles);
}

// round 15
// speedup vs baseline: 1.0716x; 1.0716x over previous
#include <cuda_runtime.h>
#include <cuda_fp16.h>
#include <math.h>
#include <stdint.h>

#define H 512
#define F 1024
#define E 16
#define MAX_T 8192
#define EPS 1e-5f

// Per-compile-pass feature detection: tcgen05 only legal on sm_103a-style targets.
#if defined(__CUDA_ARCH__) && (defined(__CUDA_ARCH_FEAT_SM103_ALL) || \
    defined(__CUDA_ARCH_FEAT_SM100_ALL) || defined(__CUDA_ARCH_SPECIFIC__) || \
    defined(__CUDA_ARCH_FAMILY_SPECIFIC__))
#define USE_TC 1
#else
#define USE_TC 0
#endif

// ---------------------------------------------------------------------------
// Scratch (no allocation allowed -> device globals)
// ---------------------------------------------------------------------------
__device__ __align__(128) __half g_x[(size_t)MAX_T * H];
__device__ __align__(128) __half g_w1t[(size_t)E * F * H];   // [e][f][h]
__device__ __align__(128) __half g_w2t[(size_t)E * H * F];   // [e][h][f]
__device__ float g_b1part[8][E * F];
__device__ __align__(128) __half g_h[(size_t)E * MAX_T * F]; // [e][t][f]

// Self-resetting counter (proven R10-R13): low16 = producers, high16 = consumers;
// last consumer zeroes the word. Zero-init at load; invariant across replays.
__device__ unsigned g_cH[(MAX_T / 128) * E];   // prod 8, cons 4

// ---------------------------------------------------------------------------
// Common helpers
// ---------------------------------------------------------------------------
__device__ __forceinline__ uint32_t smem_to_u32(const void* p) {
    uint32_t a;
    asm("{ .reg .u64 t; cvta.to.shared.u64 t, %1; cvt.u32.u64 %0, t; }" : "=r"(a) : "l"(p));
    return a;
}
#define SMEM_SWIZZLE_128B(o) ((o) ^ (((o) >> 3) & 0x70))

__device__ __forceinline__ void cpa16(uint32_t dst, const void* src) {
    asm volatile("cp.async.cg.shared.global [%0], [%1], 16;" :: "r"(dst), "l"(src));
}
#define CP_COMMIT() asm volatile("cp.async.commit_group;" ::: "memory")
__device__ __forceinline__ void cp_wait1() { asm volatile("cp.async.wait_group 1;" ::: "memory"); }
__device__ __forceinline__ void cp_wait0() { asm volatile("cp.async.wait_group 0;" ::: "memory"); }

__device__ __forceinline__ float gelu_erf(float x) {
    return 0.5f * x * (1.0f + erff(x * 0.70710678118654752f));
}

// Counter ops
__device__ __forceinline__ void ctr_release(unsigned* c) {
    asm volatile("red.release.gpu.global.add.u32 [%0], 1;" :: "l"(c) : "memory");
}
__device__ __forceinline__ unsigned ld_acq(const unsigned* c) {
    unsigned v;
    asm volatile("ld.acquire.gpu.global.u32 %0, [%1];" : "=r"(v) : "l"(c) : "memory");
    return v;
}
__device__ __forceinline__ void ctr_wait_consume(unsigned* c, unsigned target, unsigned ncons) {
    unsigned v;
    do {
        v = ld_acq(c);
        if ((v & 0xFFFFu) >= target) break;
        __nanosleep(256);
    } while (true);
    unsigned old = atomicAdd(c, 1u << 16);
    if ((old >> 16) == ncons - 1) atomicExch(c, 0u);
}

// Tile geometry: M=128 tokens, N=128, K-step=64
// SMEM stage: A(16K) B(16K) = 32KB; 2 stages = 64KB; 3 CTAs/SM
#define OFF_B 16384
#define STAGE_BYTES 32768
#define S_CTRL 65536             // tmem ptr (tc path)
#define S_MBAR 65552
#define S_B1   65568             // 128 floats of b1' for this fc tile
#define SMEM_BYTES 66080

// Full-stage load (A + B halves)
__device__ __forceinline__ void stage_load_async(uint32_t sbase,
    const __half* __restrict__ A, size_t as,
    const __half* __restrict__ B, size_t bs,
    int k0, int tid)
{
    #pragma unroll
    for (int it = 0; it < 4; it++) {
        int v = tid + it * 256;
        int r = v >> 3, c = v & 7;
        uint32_t off = SMEM_SWIZZLE_128B((uint32_t)(r * 128 + c * 16));
        cpa16(sbase + off,         A + (size_t)r * as + k0 + c * 8);
        cpa16(sbase + OFF_B + off, B + (size_t)r * bs + k0 + c * 8);
    }
}

// ===========================================================================
#if USE_TC
// tcgen05 path: one M=128 x N=128 MMA region (2-stage pipeline)
// ===========================================================================
__device__ __forceinline__ uint32_t elect_one_pred() {
    uint32_t pred;
    asm volatile("{\n\t.reg .pred p;\n\telect.sync _|p, 0xFFFFFFFF;\n\t"
                 "selp.b32 %0, 1, 0, p;\n\t}" : "=r"(pred));
    return pred;
}
static constexpr uint64_t SMEM_DESC_BASE_SW128 =
    (uint64_t(2) << 61) | (uint64_t(1) << 46) | (uint64_t(64) << 32) | (uint64_t(1) << 16);
#define MAKE_SMEM_DESC(a) (SMEM_DESC_BASE_SW128 | ((uint64_t)((a) >> 4) & 0x3FFF))

#define TCGEN05_ALLOC(sr, n) \
    asm volatile("tcgen05.alloc.cta_group::1.sync.aligned.shared::cta.b32 [%0], %1;" \
                 :: "r"((uint32_t)(sr)), "r"((uint32_t)(n)) : "memory")
#define TCGEN05_DEALLOC(t, n) \
    asm volatile("tcgen05.dealloc.cta_group::1.sync.aligned.b32 %0, %1;" :: "r"(t), "r"(n))
#define TCGEN05_RELINQUISH() \
    asm volatile("tcgen05.relinquish_alloc_permit.cta_group::1.sync.aligned;")
#define TCGEN05_COMMIT(m) \
    asm volatile("tcgen05.commit.cta_group::1.mbarrier::arrive::one.shared::cluster.b64 [%0];" \
                 :: "r"((uint32_t)(m)) : "memory")
#define TCGEN05_FENCE_AFTER() asm volatile("tcgen05.fence::after_thread_sync;" ::: "memory")
#define TCGEN05_WAIT_LD() asm volatile("tcgen05.wait::ld.sync.aligned;" ::: "memory")
#define MBARRIER_INIT(m, c) \
    asm volatile("mbarrier.init.shared.b64 [%0], %1;" :: "r"((uint32_t)(m)), "r"((uint32_t)(c)) : "memory")
#define MBARRIER_INVAL(m) \
    asm volatile("mbarrier.inval.shared.b64 [%0];" :: "r"((uint32_t)(m)) : "memory")

#define MBARRIER_WAIT_PARITY(mb, ph) do {                                         \
    uint32_t _m = (uint32_t)(mb), _p = (uint32_t)(ph), _d;                         \
    asm volatile("{\n\t.reg .pred p;\n\t"                                          \
        "mbarrier.try_wait.parity.acquire.cta.shared::cta.b64 p, [%1], %2;\n\t"    \
        "selp.b32 %0, 1, 0, p;\n\t}" : "=r"(_d) : "r"(_m), "r"(_p) : "memory");    \
    if (!_d) {                                                                     \
        asm volatile("{\n\t.reg .pred P1;\n\t"                                     \
            "WL_%=:\n\t"                                                           \
            "mbarrier.try_wait.parity.acquire.cta.shared::cta.b64 P1, [%0], %1, 0x989680;\n\t" \
            "@P1 bra.uni WD_%=;\n\t"                                               \
            "bra.uni WL_%=;\n\t"                                                   \
            "WD_%=:\n\t}" :: "r"(_m), "r"(_p) : "memory");                         \
    }                                                                              \
} while (0)

#define TCGEN05_LD_X32(r, a)                                                       \
    asm volatile("tcgen05.ld.sync.aligned.32x32b.x32.b32 "                         \
        "{%0, %1, %2, %3, %4, %5, %6, %7, %8, %9, %10, %11, %12, %13, %14, %15, "  \
        " %16, %17, %18, %19, %20, %21, %22, %23, %24, %25, %26, %27, %28, %29, %30, %31}, [%32];" \
        : "=r"((r)[0]), "=r"((r)[1]), "=r"((r)[2]), "=r"((r)[3]),                  \
          "=r"((r)[4]), "=r"((r)[5]), "=r"((r)[6]), "=r"((r)[7]),                  \
          "=r"((r)[8]), "=r"((r)[9]), "=r"((r)[10]), "=r"((r)[11]),                \
          "=r"((r)[12]), "=r"((r)[13]), "=r"((r)[14]), "=r"((r)[15]),              \
          "=r"((r)[16]), "=r"((r)[17]), "=r"((r)[18]), "=r"((r)[19]),              \
          "=r"((r)[20]), "=r"((r)[21]), "=r"((r)[22]), "=r"((r)[23]),              \
          "=r"((r)[24]), "=r"((r)[25]), "=r"((r)[26]), "=r"((r)[27]),              \
          "=r"((r)[28]), "=r"((r)[29]), "=r"((r)[30]), "=r"((r)[31])               \
        : "r"(a))

__device__ __forceinline__ void mma_f16_ss(uint32_t d_tmem, uint64_t a_desc,
                                           uint64_t b_desc, uint32_t idesc, bool acc) {
    uint32_t en = acc ? 1u : 0u;
    asm volatile("{\n\t.reg .pred p;\n\tsetp.ne.u32 p, %4, 0;\n\t"
                 "tcgen05.mma.cta_group::1.kind::f16 [%0], %1, %2, %3, p;\n\t}"
                 :: "r"(d_tmem), "l"(a_desc), "l"(b_desc), "r"(idesc), "r"(en)
                 : "memory");
}
#define MMA_IDESC ((1u << 4) | ((128u / 8u) << 17) | ((128u / 16u) << 24))

__device__ __forceinline__ uint32_t tc_prologue(uint32_t su, int tid, int wid) {
    if (wid == 0) TCGEN05_ALLOC(su + S_CTRL, 128);
    if (tid == 128) MBARRIER_INIT(su + S_MBAR, 1);
    __syncthreads();
    uint32_t tmem;
    asm volatile("ld.shared.b32 %0, [%1];" : "=r"(tmem) : "r"(su + S_CTRL));
    if (wid == 0) TCGEN05_RELINQUISH();
    __syncthreads();
    return tmem;
}

__device__ __forceinline__ void tc_mainloop(uint32_t su, uint32_t tmem,
    const __half* __restrict__ A, size_t as,
    const __half* __restrict__ B, size_t bs,
    int K, int tid, int wid)
{
    const int nk = K / 64;
    stage_load_async(su, A, as, B, bs, 0, tid);
    CP_COMMIT();
    for (int ks = 0; ks < nk; ks++) {
        if (ks > 0) MBARRIER_WAIT_PARITY(su + S_MBAR, (ks - 1) & 1);
        if (ks + 1 < nk) {
            stage_load_async(su + ((ks + 1) & 1) * STAGE_BYTES,
                             A, as, B, bs, (ks + 1) * 64, tid);
            CP_COMMIT();
            cp_wait1();
        } else {
            cp_wait0();
        }
        __syncthreads();
        if (wid == 0 && elect_one_pred()) {
            asm volatile("fence.proxy.async.shared::cta;" ::: "memory");
            uint32_t sb = su + (ks & 1) * STAGE_BYTES;
            uint64_t dA = MAKE_SMEM_DESC(sb);
            uint64_t dB = MAKE_SMEM_DESC(sb + OFF_B);
            #pragma unroll
            for (int kk = 0; kk < 4; kk++) {
                bool acc0 = (ks > 0) || (kk > 0);
                mma_f16_ss(tmem, dA + kk * 2, dB + kk * 2, MMA_IDESC, acc0);
            }
            TCGEN05_COMMIT(su + S_MBAR);
        }
        __syncthreads();
    }
    MBARRIER_WAIT_PARITY(su + S_MBAR, (nk - 1) & 1);
    TCGEN05_FENCE_AFTER();
}

__device__ __forceinline__ void tc_release_tm(uint32_t su, uint32_t tmem, int tid, int wid) {
    __syncthreads();
    if (tid == 128) MBARRIER_INVAL(su + S_MBAR);
    __syncthreads();
    if (wid == 0) TCGEN05_DEALLOC(tmem, 128);
}
#endif  // USE_TC

// ===========================================================================
#if !USE_TC
// mma.sync fallback: 8 warps, warp tile 32x64, 2-stage pipeline
// ===========================================================================
__device__ __forceinline__ void ldsm_x4(uint32_t* r, uint32_t a) {
    asm volatile("ldmatrix.sync.aligned.m8n8.x4.shared.b16 {%0,%1,%2,%3}, [%4];"
                 : "=r"(r[0]), "=r"(r[1]), "=r"(r[2]), "=r"(r[3]) : "r"(a));
}
__device__ __forceinline__ void mma16816(float* d, const uint32_t* a, const uint32_t* b) {
    asm volatile("mma.sync.aligned.m16n8k16.row.col.f32.f16.f16.f32 "
                 "{%0,%1,%2,%3}, {%4,%5,%6,%7}, {%8,%9}, {%0,%1,%2,%3};"
                 : "+f"(d[0]), "+f"(d[1]), "+f"(d[2]), "+f"(d[3])
                 : "r"(a[0]), "r"(a[1]), "r"(a[2]), "r"(a[3]), "r"(b[0]), "r"(b[1]));
}

__device__ __forceinline__ void mmasync_mainloop(uint32_t su,
    const __half* __restrict__ A, size_t as,
    const __half* __restrict__ B, size_t bs,
    int K, int tid, float acc[2][8][4])
{
    const int nk = K / 64;
    const int wid = tid >> 5, lane = tid & 31;
    const int wm = wid >> 1, wn = wid & 1;

    stage_load_async(su, A, as, B, bs, 0, tid);
    CP_COMMIT();

    for (int ks = 0; ks < nk; ks++) {
        if (ks + 1 < nk) {
            stage_load_async(su + ((ks + 1) & 1) * STAGE_BYTES,
                             A, as, B, bs, (ks + 1) * 64, tid);
            CP_COMMIT();
            cp_wait1();
        } else {
            cp_wait0();
        }
        __syncthreads();

        uint32_t sA = su + (ks & 1) * STAGE_BYTES;
        uint32_t sB = sA + OFF_B;

        #pragma unroll
        for (int k16 = 0; k16 < 64; k16 += 16) {
            uint32_t bh[8][2];
            #pragma unroll
            for (int jj = 0; jj < 4; jj++) {
                int n = wn * 64 + jj * 16 + (lane & 7) + ((lane >> 3) & 1) * 8;
                int k = k16 + (lane >> 4) * 8;
                uint32_t addr = sB + SMEM_SWIZZLE_128B((uint32_t)(n * 128 + k * 2));
                uint32_t t[4];
                ldsm_x4(t, addr);
                bh[2 * jj][0] = t[0]; bh[2 * jj + 1][0] = t[1];
                bh[2 * jj][1] = t[2]; bh[2 * jj + 1][1] = t[3];
            }
            #pragma unroll
            for (int i = 0; i < 2; i++) {
                int m = wm * 32 + i * 16 + (lane & 15);
                int k = k16 + (lane >> 4) * 8;
                uint32_t addr = sA + SMEM_SWIZZLE_128B((uint32_t)(m * 128 + k * 2));
                uint32_t ah[4];
                ldsm_x4(ah, addr);
                #pragma unroll
                for (int j = 0; j < 8; j++)
                    mma16816(acc[i][j], ah, bh[j]);
            }
        }
        __syncthreads();
    }
}
#endif  // !USE_TC

// ---------------------------------------------------------------------------
// Prep kernel (high occupancy): LN + W1^T*g + b1 partials + W2^T
// ---------------------------------------------------------------------------
__global__ void __launch_bounds__(256) prep_kernel(
    const float* __restrict__ tokens, const float* __restrict__ ln_g,
    const float* __restrict__ ln_b,   const float* __restrict__ W1,
    const float* __restrict__ W2,     int nbLN)
{
    __shared__ float ts[64][65];
    __shared__ float ps[4][64];
    const int tid = threadIdx.x;
    int b = blockIdx.x;

    if (b < nbLN) {
        const int wid = tid >> 5, lane = tid & 31;
        const int row = b * 8 + wid;
        const float* x = tokens + (size_t)row * H;
        float v[16];
        float s = 0.0f;
        #pragma unroll
        for (int i = 0; i < 16; i++) { v[i] = x[lane + 32 * i]; s += v[i]; }
        #pragma unroll
        for (int o = 16; o > 0; o >>= 1) s += __shfl_xor_sync(0xffffffffu, s, o);
        float mu = s * (1.0f / H);
        float q = 0.0f;
        #pragma unroll
        for (int i = 0; i < 16; i++) { v[i] -= mu; q += v[i] * v[i]; }
        #pragma unroll
        for (int o = 16; o > 0; o >>= 1) q += __shfl_xor_sync(0xffffffffu, q, o);
        float rs = rsqrtf(q * (1.0f / H) + EPS);
        __half* ox = g_x + (size_t)row * H;
        #pragma unroll
        for (int i = 0; i < 16; i++)
            ox[lane + 32 * i] = __float2half_rn(v[i] * rs);
        return;
    }
    b -= nbLN;

    if (b < 2048) {
        // ---- W1^T * g + b1 partials ----
        int f0 = (b & 15) * 64, h0 = ((b >> 4) & 7) * 64, e = b >> 7;
        #pragma unroll
        for (int i = 0; i < 16; i++) {
            int idx = tid + i * 256, r = idx >> 6, c = idx & 63;
            ts[r][c] = W1[((size_t)e * H + h0 + r) * F + f0 + c];
        }
        __syncthreads();
        #pragma unroll
        for (int i = 0; i < 16; i++) {
            int idx = tid + i * 256, r = idx >> 6, c = idx & 63;
            float w = ts[c][r] * ln_g[e * H + h0 + c];
            g_w1t[((size_t)e * F + f0 + r) * H + h0 + c] = __float2half_rn(w);
        }
        {
            int f = tid & 63, q = tid >> 6;
            const float* lb = ln_b + e * H + h0 + q * 16;
            float s = 0.0f;
            #pragma unroll
            for (int r = 0; r < 16; r++) s += lb[r] * ts[q * 16 + r][f];
            ps[q][f] = s;
        }
        __syncthreads();
        if (tid < 64) {
            float a = ps[0][tid] + ps[1][tid] + ps[2][tid] + ps[3][tid];
            g_b1part[h0 >> 6][e * F + f0 + tid] = a;
        }
        return;
    }
    b -= 2048;

    // ---- W2^T ----
    {
        int h0 = (b & 7) * 64, f0 = ((b >> 3) & 15) * 64, e = b >> 7;
        #pragma unroll
        for (int i = 0; i < 16; i++) {
            int idx = tid + i * 256, r = idx >> 6, c = idx & 63;
            ts[r][c] = W2[((size_t)e * F + f0 + r) * H + h0 + c];
        }
        __syncthreads();
        #pragma unroll
        for (int i = 0; i < 16; i++) {
            int idx = tid + i * 256, r = idx >> 6, c = idx & 63;
            g_w2t[((size_t)e * H + h0 + r) * F + f0 + c] = __float2half_rn(ts[c][r]);
        }
    }
}

// ---------------------------------------------------------------------------
// Fused GEMM kernel: [GEMM1 nb1][GEMM2 nb2], 3 CTAs/SM, 2-stage pipeline
// ---------------------------------------------------------------------------
__global__ void __launch_bounds__(256, 3) gemm_fused_kernel(
    const float* __restrict__ b1, const float* __restrict__ b2,
    float* __restrict__ out, int tiles)
{
    extern __shared__ char smem[];
    uint32_t su = smem_to_u32(smem);
    const int tid = threadIdx.x, wid = tid >> 5, lane = tid & 31;
    const int nb1 = tiles * E * 8;
    int b = blockIdx.x;

    if (b < nb1) {
        // ================= GEMM1 producer =================
        const int t = b >> 7;
        const int e = (b >> 3) & 15;
        const int fc = (b & 7) * 128;
        const int tok0 = t * 128;
        float* sm_b1 = reinterpret_cast<float*>(smem + S_B1);

        if (tid < 128) {
            int fg = e * F + fc + tid;
            float a = b1[fg];
            #pragma unroll
            for (int s = 0; s < 8; s++) a += g_b1part[s][fg];
            sm_b1[tid] = a;
        }

        const __half* A = g_x + (size_t)tok0 * H;
        const __half* B = g_w1t + ((size_t)e * F + fc) * H;

#if USE_TC
        uint32_t tmem = tc_prologue(su, tid, wid);
        tc_mainloop(su, tmem, A, H, B, H, H, tid, wid);
        const int row = (wid & 3) * 32 + lane;
        const int ch = (wid >> 2) * 64;
        const size_t hrow = ((size_t)e * MAX_T + tok0 + row) * F;
        for (int cb = 0; cb < 64; cb += 32) {
            uint32_t r[32];
            TCGEN05_LD_X32(r, tmem + ch + cb);
            TCGEN05_WAIT_LD();
            int fglob = fc + ch + cb;
            __half h8[8];
            #pragma unroll
            for (int j = 0; j < 32; j++) {
                float v = __uint_as_float(r[j]) + sm_b1[ch + cb + j];
                h8[j & 7] = __float2half_rn(gelu_erf(v));
                if ((j & 7) == 7)
                    *reinterpret_cast<uint4*>(&g_h[hrow + fglob + (j & ~7)]) =
                        *reinterpret_cast<uint4*>(h8);
            }
        }
        tc_release_tm(su, tmem, tid, wid);
#else
        float acc[2][8][4];
        #pragma unroll
        for (int i = 0; i < 2; i++)
            #pragma unroll
            for (int j = 0; j < 8; j++)
                #pragma unroll
                for (int q = 0; q < 4; q++) acc[i][j][q] = 0.0f;

        mmasync_mainloop(su, A, H, B, H, H, tid, acc);

        const int wm = wid >> 1, wn = wid & 1;
        #pragma unroll
        for (int i = 0; i < 2; i++) {
            #pragma unroll
            for (int j = 0; j < 8; j++) {
                int fl = wn * 64 + j * 8 + (lane & 3) * 2;
                int r0 = tok0 + wm * 32 + i * 16 + (lane >> 2);
                float bb0 = sm_b1[fl], bb1 = sm_b1[fl + 1];
                #pragma unroll
                for (int half = 0; half < 2; half++) {
                    int rr = r0 + half * 8;
                    float v0 = acc[i][j][2 * half + 0] + bb0;
                    float v1 = acc[i][j][2 * half + 1] + bb1;
                    __half h0 = __float2half_rn(gelu_erf(v0));
                    __half h1 = __float2half_rn(gelu_erf(v1));
                    uint32_t ph = ((uint32_t)__half_as_ushort(h1) << 16) | __half_as_ushort(h0);
                    *reinterpret_cast<uint32_t*>(&g_h[((size_t)e * MAX_T + rr) * F + fc + fl]) = ph;
                }
            }
        }
#endif
        __threadfence();
        __syncthreads();
        if (tid == 0) ctr_release(&g_cH[t * E + e]);
        return;
    }
    b -= nb1;

    // ================= GEMM2 consumer =================
    {
        const int t = b >> 6;
        const int e = (b >> 2) & 15;
        const int hh0 = (b & 3) * 128;
        const int tok0 = t * 128;

        if (tid == 0) ctr_wait_consume(&g_cH[t * E + e], 8u, 4u);
        __syncthreads();
        __threadfence();

        const __half* A = g_h + ((size_t)e * MAX_T + tok0) * F;
        const __half* B = g_w2t + ((size_t)e * H + hh0) * F;

#if USE_TC
        uint32_t tmem = tc_prologue(su, tid, wid);
        tc_mainloop(su, tmem, A, F, B, F, F, tid, wid);
        const int row = (wid & 3) * 32 + lane;
        const int ch = (wid >> 2) * 64;
        float* orow = out + (((size_t)(tok0 + row)) * E + e) * H;
        for (int cb = 0; cb < 64; cb += 32) {
            uint32_t r[32];
            TCGEN05_LD_X32(r, tmem + ch + cb);
            TCGEN05_WAIT_LD();
            int hglob = hh0 + ch + cb;
            float v4[4];
            #pragma unroll
            for (int j = 0; j < 32; j++) {
                v4[j & 3] = __uint_as_float(r[j]) + b2[e * H + hglob + j];
                if ((j & 3) == 3)
                    *reinterpret_cast<uint4*>(orow + hglob + (j & ~3)) =
                        *reinterpret_cast<uint4*>(v4);
            }
        }
        tc_release_tm(su, tmem, tid, wid);
#else
        float acc[2][8][4];
        #pragma unroll
        for (int i = 0; i < 2; i++)
            #pragma unroll
            for (int j = 0; j < 8; j++)
                #pragma unroll
                for (int q = 0; q < 4; q++) acc[i][j][q] = 0.0f;

        mmasync_mainloop(su, A, F, B, F, F, tid, acc);

        const int wm = wid >> 1, wn = wid & 1;
        const float* b2p = b2 + e * H;
        #pragma unroll
        for (int i = 0; i < 2; i++) {
            #pragma unroll
            for (int j = 0; j < 8; j++) {
                int hj = hh0 + wn * 64 + j * 8 + (lane & 3) * 2;
                int r0 = tok0 + wm * 32 + i * 16 + (lane >> 2);
                float bb0 = b2p[hj], bb1 = b2p[hj + 1];
                #pragma unroll
                for (int half = 0; half < 2; half++) {
                    int rr = r0 + half * 8;
                    float2 v = make_float2(acc[i][j][2 * half + 0] + bb0,
                                           acc[i][j][2 * half + 1] + bb1);
                    *reinterpret_cast<float2*>(out + ((size_t)rr * E + e) * H + hj) = v;
                }
            }
        }
#endif
    }
}

// ---------------------------------------------------------------------------
extern "C" void kernel_launch(void* const* d_in, const int* in_sizes, int n_in,
                              void* d_out, int out_size)
{
    const float* tokens = (const float*)d_in[0];
    const float* ln_g   = (const float*)d_in[1];
    const float* ln_b   = (const float*)d_in[2];
    const float* W1     = (const float*)d_in[3];
    const float* b1     = (const float*)d_in[4];
    const float* W2     = (const float*)d_in[5];
    const float* b2     = (const float*)d_in[6];
    float* out = (float*)d_out;

    int T = in_sizes[0] / H;      // 8192
    int tiles = T / 128;          // 64
    int nbLN = T / 8;             // 1024

    cudaFuncSetAttribute(gemm_fused_kernel, cudaFuncAttributeMaxDynamicSharedMemorySize, SMEM_BYTES);

    prep_kernel<<<nbLN + 4096, 256>>>(tokens, ln_g, ln_b, W1, W2, nbLN);

    int ng = tiles * E * 8 + tiles * E * 4;   // 12288
    gemm_fused_kernel<<<ng, 256, SMEM_BYTES>>>(b1, b2, out, tiles);
}

// round 16
// speedup vs baseline: 1.1160x; 1.0414x over previous
#include <cuda_runtime.h>
#include <cuda_fp16.h>
#include <math.h>
#include <stdint.h>

#define H 512
#define F 1024
#define E 16
#define MAX_T 8192
#define EPS 1e-5f

// Per-compile-pass feature detection: tcgen05 only legal on sm_103a-style targets.
#if defined(__CUDA_ARCH__) && (defined(__CUDA_ARCH_FEAT_SM103_ALL) || \
    defined(__CUDA_ARCH_FEAT_SM100_ALL) || defined(__CUDA_ARCH_SPECIFIC__) || \
    defined(__CUDA_ARCH_FAMILY_SPECIFIC__))
#define USE_TC 1
#else
#define USE_TC 0
#endif

// ---------------------------------------------------------------------------
// Scratch (no allocation allowed -> device globals)
// ---------------------------------------------------------------------------
__device__ __align__(128) __half g_x[(size_t)MAX_T * H];
__device__ __align__(128) __half g_w1t[(size_t)E * F * H];   // [e][f][h]
__device__ __align__(128) __half g_w2t[(size_t)E * H * F];   // [e][h][f]
__device__ float g_b1part[8][E * F];
__device__ __align__(128) __half g_h[(size_t)E * MAX_T * F]; // [e][t][f]

// Self-resetting counter (proven R10-R13): low16 = producers, high16 = consumers;
// last consumer zeroes the word. Zero-init at load; invariant across replays.
__device__ unsigned g_cH[(MAX_T / 128) * E];   // prod 8, cons 4

// ---------------------------------------------------------------------------
// Common helpers
// ---------------------------------------------------------------------------
__device__ __forceinline__ uint32_t smem_to_u32(const void* p) {
    uint32_t a;
    asm("{ .reg .u64 t; cvta.to.shared.u64 t, %1; cvt.u32.u64 %0, t; }" : "=r"(a) : "l"(p));
    return a;
}
#define SMEM_SWIZZLE_128B(o) ((o) ^ (((o) >> 3) & 0x70))

__device__ __forceinline__ void cpa16(uint32_t dst, const void* src) {
    asm volatile("cp.async.cg.shared.global [%0], [%1], 16;" :: "r"(dst), "l"(src));
}
#define CP_COMMIT() asm volatile("cp.async.commit_group;" ::: "memory")
__device__ __forceinline__ void cp_wait1() { asm volatile("cp.async.wait_group 1;" ::: "memory"); }
__device__ __forceinline__ void cp_wait0() { asm volatile("cp.async.wait_group 0;" ::: "memory"); }

__device__ __forceinline__ float gelu_erf(float x) {
    return 0.5f * x * (1.0f + erff(x * 0.70710678118654752f));
}

// Counter ops
__device__ __forceinline__ void ctr_release(unsigned* c) {
    asm volatile("red.release.gpu.global.add.u32 [%0], 1;" :: "l"(c) : "memory");
}
__device__ __forceinline__ unsigned ld_acq(const unsigned* c) {
    unsigned v;
    asm volatile("ld.acquire.gpu.global.u32 %0, [%1];" : "=r"(v) : "l"(c) : "memory");
    return v;
}
__device__ __forceinline__ void ctr_wait_consume(unsigned* c, unsigned target, unsigned ncons) {
    unsigned v;
    do {
        v = ld_acq(c);
        if ((v & 0xFFFFu) >= target) break;
        __nanosleep(256);
    } while (true);
    unsigned old = atomicAdd(c, 1u << 16);
    if ((old >> 16) == ncons - 1) atomicExch(c, 0u);
}

// Tile geometry: M=128 tokens, N=128, K-step=64
// SMEM stage: A(16K) B(16K) = 32KB; 2 stages = 64KB; 3 CTAs/SM
#define OFF_B 16384
#define STAGE_BYTES 32768
#define S_CTRL 65536             // tmem ptr (tc path)
#define S_MBAR 65552
#define S_B1   65568             // 128 floats of b1' for this fc tile
#define SMEM_BYTES 66080

// Full-stage load (A + B halves)
__device__ __forceinline__ void stage_load_async(uint32_t sbase,
    const __half* __restrict__ A, size_t as,
    const __half* __restrict__ B, size_t bs,
    int k0, int tid)
{
    #pragma unroll
    for (int it = 0; it < 4; it++) {
        int v = tid + it * 256;
        int r = v >> 3, c = v & 7;
        uint32_t off = SMEM_SWIZZLE_128B((uint32_t)(r * 128 + c * 16));
        cpa16(sbase + off,         A + (size_t)r * as + k0 + c * 8);
        cpa16(sbase + OFF_B + off, B + (size_t)r * bs + k0 + c * 8);
    }
}

// ===========================================================================
#if USE_TC
// tcgen05 path: one M=128 x N=128 MMA region (2-stage pipeline)
// ===========================================================================
__device__ __forceinline__ uint32_t elect_one_pred() {
    uint32_t pred;
    asm volatile("{\n\t.reg .pred p;\n\telect.sync _|p, 0xFFFFFFFF;\n\t"
                 "selp.b32 %0, 1, 0, p;\n\t}" : "=r"(pred));
    return pred;
}
static constexpr uint64_t SMEM_DESC_BASE_SW128 =
    (uint64_t(2) << 61) | (uint64_t(1) << 46) | (uint64_t(64) << 32) | (uint64_t(1) << 16);
#define MAKE_SMEM_DESC(a) (SMEM_DESC_BASE_SW128 | ((uint64_t)((a) >> 4) & 0x3FFF))

#define TCGEN05_ALLOC(sr, n) \
    asm volatile("tcgen05.alloc.cta_group::1.sync.aligned.shared::cta.b32 [%0], %1;" \
                 :: "r"((uint32_t)(sr)), "r"((uint32_t)(n)) : "memory")
#define TCGEN05_DEALLOC(t, n) \
    asm volatile("tcgen05.dealloc.cta_group::1.sync.aligned.b32 %0, %1;" :: "r"(t), "r"(n))
#define TCGEN05_RELINQUISH() \
    asm volatile("tcgen05.relinquish_alloc_permit.cta_group::1.sync.aligned;")
#define TCGEN05_COMMIT(m) \
    asm volatile("tcgen05.commit.cta_group::1.mbarrier::arrive::one.shared::cluster.b64 [%0];" \
                 :: "r"((uint32_t)(m)) : "memory")
#define TCGEN05_FENCE_AFTER() asm volatile("tcgen05.fence::after_thread_sync;" ::: "memory")
#define TCGEN05_WAIT_LD() asm volatile("tcgen05.wait::ld.sync.aligned;" ::: "memory")
#define MBARRIER_INIT(m, c) \
    asm volatile("mbarrier.init.shared.b64 [%0], %1;" :: "r"((uint32_t)(m)), "r"((uint32_t)(c)) : "memory")
#define MBARRIER_INVAL(m) \
    asm volatile("mbarrier.inval.shared.b64 [%0];" :: "r"((uint32_t)(m)) : "memory")

#define MBARRIER_WAIT_PARITY(mb, ph) do {                                         \
    uint32_t _m = (uint32_t)(mb), _p = (uint32_t)(ph), _d;                         \
    asm volatile("{\n\t.reg .pred p;\n\t"                                          \
        "mbarrier.try_wait.parity.acquire.cta.shared::cta.b64 p, [%1], %2;\n\t"    \
        "selp.b32 %0, 1, 0, p;\n\t}" : "=r"(_d) : "r"(_m), "r"(_p) : "memory");    \
    if (!_d) {                                                                     \
        asm volatile("{\n\t.reg .pred P1;\n\t"                                     \
            "WL_%=:\n\t"                                                           \
            "mbarrier.try_wait.parity.acquire.cta.shared::cta.b64 P1, [%0], %1, 0x989680;\n\t" \
            "@P1 bra.uni WD_%=;\n\t"                                               \
            "bra.uni WL_%=;\n\t"                                                   \
            "WD_%=:\n\t}" :: "r"(_m), "r"(_p) : "memory");                         \
    }                                                                              \
} while (0)

#define TCGEN05_LD_X32(r, a)                                                       \
    asm volatile("tcgen05.ld.sync.aligned.32x32b.x32.b32 "                         \
        "{%0, %1, %2, %3, %4, %5, %6, %7, %8, %9, %10, %11, %12, %13, %14, %15, "  \
        " %16, %17, %18, %19, %20, %21, %22, %23, %24, %25, %26, %27, %28, %29, %30, %31}, [%32];" \
        : "=r"((r)[0]), "=r"((r)[1]), "=r"((r)[2]), "=r"((r)[3]),                  \
          "=r"((r)[4]), "=r"((r)[5]), "=r"((r)[6]), "=r"((r)[7]),                  \
          "=r"((r)[8]), "=r"((r)[9]), "=r"((r)[10]), "=r"((r)[11]),                \
          "=r"((r)[12]), "=r"((r)[13]), "=r"((r)[14]), "=r"((r)[15]),              \
          "=r"((r)[16]), "=r"((r)[17]), "=r"((r)[18]), "=r"((r)[19]),              \
          "=r"((r)[20]), "=r"((r)[21]), "=r"((r)[22]), "=r"((r)[23]),              \
          "=r"((r)[24]), "=r"((r)[25]), "=r"((r)[26]), "=r"((r)[27]),              \
          "=r"((r)[28]), "=r"((r)[29]), "=r"((r)[30]), "=r"((r)[31])               \
        : "r"(a))

__device__ __forceinline__ void mma_f16_ss(uint32_t d_tmem, uint64_t a_desc,
                                           uint64_t b_desc, uint32_t idesc, bool acc) {
    uint32_t en = acc ? 1u : 0u;
    asm volatile("{\n\t.reg .pred p;\n\tsetp.ne.u32 p, %4, 0;\n\t"
                 "tcgen05.mma.cta_group::1.kind::f16 [%0], %1, %2, %3, p;\n\t}"
                 :: "r"(d_tmem), "l"(a_desc), "l"(b_desc), "r"(idesc), "r"(en)
                 : "memory");
}
#define MMA_IDESC ((1u << 4) | ((128u / 8u) << 17) | ((128u / 16u) << 24))

__device__ __forceinline__ uint32_t tc_prologue(uint32_t su, int tid, int wid) {
    if (wid == 0) TCGEN05_ALLOC(su + S_CTRL, 128);
    if (tid == 128) MBARRIER_INIT(su + S_MBAR, 1);
    __syncthreads();
    uint32_t tmem;
    asm volatile("ld.shared.b32 %0, [%1];" : "=r"(tmem) : "r"(su + S_CTRL));
    if (wid == 0) TCGEN05_RELINQUISH();
    __syncthreads();
    return tmem;
}

__device__ __forceinline__ void tc_mainloop(uint32_t su, uint32_t tmem,
    const __half* __restrict__ A, size_t as,
    const __half* __restrict__ B, size_t bs,
    int K, int tid, int wid)
{
    const int nk = K / 64;
    stage_load_async(su, A, as, B, bs, 0, tid);
    CP_COMMIT();
    #pragma unroll 2
    for (int ks = 0; ks < nk; ks++) {
        if (ks > 0) MBARRIER_WAIT_PARITY(su + S_MBAR, (ks - 1) & 1);
        if (ks + 1 < nk) {
            stage_load_async(su + ((ks + 1) & 1) * STAGE_BYTES,
                             A, as, B, bs, (ks + 1) * 64, tid);
            CP_COMMIT();
            cp_wait1();
        } else {
            cp_wait0();
        }
        __syncthreads();
        if (wid == 0 && elect_one_pred()) {
            asm volatile("fence.proxy.async.shared::cta;" ::: "memory");
            uint32_t sb = su + (ks & 1) * STAGE_BYTES;
            uint64_t dA = MAKE_SMEM_DESC(sb);
            uint64_t dB = MAKE_SMEM_DESC(sb + OFF_B);
            #pragma unroll
            for (int kk = 0; kk < 4; kk++) {
                bool acc0 = (ks > 0) || (kk > 0);
                mma_f16_ss(tmem, dA + kk * 2, dB + kk * 2, MMA_IDESC, acc0);
            }
            TCGEN05_COMMIT(su + S_MBAR);
        }
        __syncthreads();
    }
    MBARRIER_WAIT_PARITY(su + S_MBAR, (nk - 1) & 1);
    TCGEN05_FENCE_AFTER();
}

__device__ __forceinline__ void tc_release_tm(uint32_t su, uint32_t tmem, int tid, int wid) {
    __syncthreads();
    if (tid == 128) MBARRIER_INVAL(su + S_MBAR);
    __syncthreads();
    if (wid == 0) TCGEN05_DEALLOC(tmem, 128);
}
#endif  // USE_TC

// ===========================================================================
#if !USE_TC
// mma.sync fallback: 8 warps, warp tile 32x64, 2-stage pipeline
// ===========================================================================
__device__ __forceinline__ void ldsm_x4(uint32_t* r, uint32_t a) {
    asm volatile("ldmatrix.sync.aligned.m8n8.x4.shared.b16 {%0,%1,%2,%3}, [%4];"
                 : "=r"(r[0]), "=r"(r[1]), "=r"(r[2]), "=r"(r[3]) : "r"(a));
}
__device__ __forceinline__ void mma16816(float* d, const uint32_t* a, const uint32_t* b) {
    asm volatile("mma.sync.aligned.m16n8k16.row.col.f32.f16.f16.f32 "
                 "{%0,%1,%2,%3}, {%4,%5,%6,%7}, {%8,%9}, {%0,%1,%2,%3};"
                 : "+f"(d[0]), "+f"(d[1]), "+f"(d[2]), "+f"(d[3])
                 : "r"(a[0]), "r"(a[1]), "r"(a[2]), "r"(a[3]), "r"(b[0]), "r"(b[1]));
}

__device__ __forceinline__ void mmasync_mainloop(uint32_t su,
    const __half* __restrict__ A, size_t as,
    const __half* __restrict__ B, size_t bs,
    int K, int tid, float acc[2][8][4])
{
    const int nk = K / 64;
    const int wid = tid >> 5, lane = tid & 31;
    const int wm = wid >> 1, wn = wid & 1;

    // Precompute ks-invariant swizzled offsets (relative to stage base).
    uint32_t offB[4], offA[2];
    {
        int k = (lane >> 4) * 8;
        #pragma unroll
        for (int jj = 0; jj < 4; jj++) {
            int n = wn * 64 + jj * 16 + (lane & 7) + ((lane >> 3) & 1) * 8;
            offB[jj] = OFF_B + SMEM_SWIZZLE_128B((uint32_t)(n * 128 + k * 2));
        }
        #pragma unroll
        for (int i = 0; i < 2; i++) {
            int m = wm * 32 + i * 16 + (lane & 15);
            offA[i] = SMEM_SWIZZLE_128B((uint32_t)(m * 128 + k * 2));
        }
    }

    stage_load_async(su, A, as, B, bs, 0, tid);
    CP_COMMIT();

    #pragma unroll 2
    for (int ks = 0; ks < nk; ks++) {
        if (ks + 1 < nk) {
            stage_load_async(su + ((ks + 1) & 1) * STAGE_BYTES,
                             A, as, B, bs, (ks + 1) * 64, tid);
            CP_COMMIT();
            cp_wait1();
        } else {
            cp_wait0();
        }
        __syncthreads();

        uint32_t sA = su + (ks & 1) * STAGE_BYTES;

        #pragma unroll
        for (int k16 = 0; k16 < 64; k16 += 16) {
            // k16 advances the k byte offset by 32; bits [4:6] of the offset
            // participate in the swizzle XOR, but k16*2 = 32,64,96 only touch
            // bits >= 5 and < 7... use XOR-safe add: k*2 < 128 keeps row bits
            // constant, and the swizzle mask depends only on row bits, so
            // adding k16*2 to the swizzled offset is exact.
            uint32_t kadd = (uint32_t)(k16 * 2);
            uint32_t bh[8][2];
            #pragma unroll
            for (int jj = 0; jj < 4; jj++) {
                uint32_t t[4];
                ldsm_x4(t, sA + offB[jj] + kadd);
                bh[2 * jj][0] = t[0]; bh[2 * jj + 1][0] = t[1];
                bh[2 * jj][1] = t[2]; bh[2 * jj + 1][1] = t[3];
            }
            #pragma unroll
            for (int i = 0; i < 2; i++) {
                uint32_t ah[4];
                ldsm_x4(ah, sA + offA[i] + kadd);
                #pragma unroll
                for (int j = 0; j < 8; j++)
                    mma16816(acc[i][j], ah, bh[j]);
            }
        }
        __syncthreads();
    }
}
#endif  // !USE_TC

// ---------------------------------------------------------------------------
// Prep kernel (high occupancy): LN + W1^T*g + b1 partials + W2^T
// ---------------------------------------------------------------------------
__global__ void __launch_bounds__(256) prep_kernel(
    const float* __restrict__ tokens, const float* __restrict__ ln_g,
    const float* __restrict__ ln_b,   const float* __restrict__ W1,
    const float* __restrict__ W2,     int nbLN)
{
    __shared__ float ts[64][65];
    __shared__ float ps[4][64];
    const int tid = threadIdx.x;
    int b = blockIdx.x;

    if (b < nbLN) {
        const int wid = tid >> 5, lane = tid & 31;
        const int row = b * 8 + wid;
        const float* x = tokens + (size_t)row * H;
        float v[16];
        float s = 0.0f;
        #pragma unroll
        for (int i = 0; i < 16; i++) { v[i] = x[lane + 32 * i]; s += v[i]; }
        #pragma unroll
        for (int o = 16; o > 0; o >>= 1) s += __shfl_xor_sync(0xffffffffu, s, o);
        float mu = s * (1.0f / H);
        float q = 0.0f;
        #pragma unroll
        for (int i = 0; i < 16; i++) { v[i] -= mu; q += v[i] * v[i]; }
        #pragma unroll
        for (int o = 16; o > 0; o >>= 1) q += __shfl_xor_sync(0xffffffffu, q, o);
        float rs = rsqrtf(q * (1.0f / H) + EPS);
        __half* ox = g_x + (size_t)row * H;
        #pragma unroll
        for (int i = 0; i < 16; i++)
            ox[lane + 32 * i] = __float2half_rn(v[i] * rs);
        return;
    }
    b -= nbLN;

    if (b < 2048) {
        // ---- W1^T * g + b1 partials ----
        int f0 = (b & 15) * 64, h0 = ((b >> 4) & 7) * 64, e = b >> 7;
        #pragma unroll
        for (int i = 0; i < 16; i++) {
            int idx = tid + i * 256, r = idx >> 6, c = idx & 63;
            ts[r][c] = W1[((size_t)e * H + h0 + r) * F + f0 + c];
        }
        __syncthreads();
        #pragma unroll
        for (int i = 0; i < 16; i++) {
            int idx = tid + i * 256, r = idx >> 6, c = idx & 63;
            float w = ts[c][r] * ln_g[e * H + h0 + c];
            g_w1t[((size_t)e * F + f0 + r) * H + h0 + c] = __float2half_rn(w);
        }
        {
            int f = tid & 63, q = tid >> 6;
            const float* lb = ln_b + e * H + h0 + q * 16;
            float s = 0.0f;
            #pragma unroll
            for (int r = 0; r < 16; r++) s += lb[r] * ts[q * 16 + r][f];
            ps[q][f] = s;
        }
        __syncthreads();
        if (tid < 64) {
            float a = ps[0][tid] + ps[1][tid] + ps[2][tid] + ps[3][tid];
            g_b1part[h0 >> 6][e * F + f0 + tid] = a;
        }
        return;
    }
    b -= 2048;

    // ---- W2^T ----
    {
        int h0 = (b & 7) * 64, f0 = ((b >> 3) & 15) * 64, e = b >> 7;
        #pragma unroll
        for (int i = 0; i < 16; i++) {
            int idx = tid + i * 256, r = idx >> 6, c = idx & 63;
            ts[r][c] = W2[((size_t)e * F + f0 + r) * H + h0 + c];
        }
        __syncthreads();
        #pragma unroll
        for (int i = 0; i < 16; i++) {
            int idx = tid + i * 256, r = idx >> 6, c = idx & 63;
            g_w2t[((size_t)e * H + h0 + r) * F + f0 + c] = __float2half_rn(ts[c][r]);
        }
    }
}

// ---------------------------------------------------------------------------
// Fused GEMM kernel: [GEMM1 nb1][GEMM2 nb2], 3 CTAs/SM, 2-stage pipeline
// ---------------------------------------------------------------------------
__global__ void __launch_bounds__(256, 3) gemm_fused_kernel(
    const float* __restrict__ b1, const float* __restrict__ b2,
    float* __restrict__ out, int tiles)
{
    extern __shared__ char smem[];
    uint32_t su = smem_to_u32(smem);
    const int tid = threadIdx.x, wid = tid >> 5, lane = tid & 31;
    const int nb1 = tiles * E * 8;
    int b = blockIdx.x;

    if (b < nb1) {
        // ================= GEMM1 producer =================
        const int t = b >> 7;
        const int e = (b >> 3) & 15;
        const int fc = (b & 7) * 128;
        const int tok0 = t * 128;
        float* sm_b1 = reinterpret_cast<float*>(smem + S_B1);

        if (tid < 128) {
            int fg = e * F + fc + tid;
            float a = b1[fg];
            #pragma unroll
            for (int s = 0; s < 8; s++) a += g_b1part[s][fg];
            sm_b1[tid] = a;
        }

        const __half* A = g_x + (size_t)tok0 * H;
        const __half* B = g_w1t + ((size_t)e * F + fc) * H;

#if USE_TC
        uint32_t tmem = tc_prologue(su, tid, wid);
        tc_mainloop(su, tmem, A, H, B, H, H, tid, wid);
        const int row = (wid & 3) * 32 + lane;
        const int ch = (wid >> 2) * 64;
        const size_t hrow = ((size_t)e * MAX_T + tok0 + row) * F;
        for (int cb = 0; cb < 64; cb += 32) {
            uint32_t r[32];
            TCGEN05_LD_X32(r, tmem + ch + cb);
            TCGEN05_WAIT_LD();
            int fglob = fc + ch + cb;
            __half h8[8];
            #pragma unroll
            for (int j = 0; j < 32; j++) {
                float v = __uint_as_float(r[j]) + sm_b1[ch + cb + j];
                h8[j & 7] = __float2half_rn(gelu_erf(v));
                if ((j & 7) == 7)
                    *reinterpret_cast<uint4*>(&g_h[hrow + fglob + (j & ~7)]) =
                        *reinterpret_cast<uint4*>(h8);
            }
        }
        tc_release_tm(su, tmem, tid, wid);
#else
        float acc[2][8][4];
        #pragma unroll
        for (int i = 0; i < 2; i++)
            #pragma unroll
            for (int j = 0; j < 8; j++)
                #pragma unroll
                for (int q = 0; q < 4; q++) acc[i][j][q] = 0.0f;

        mmasync_mainloop(su, A, H, B, H, H, tid, acc);

        const int wm = wid >> 1, wn = wid & 1;
        #pragma unroll
        for (int i = 0; i < 2; i++) {
            #pragma unroll
            for (int j = 0; j < 8; j++) {
                int fl = wn * 64 + j * 8 + (lane & 3) * 2;
                int r0 = tok0 + wm * 32 + i * 16 + (lane >> 2);
                float bb0 = sm_b1[fl], bb1 = sm_b1[fl + 1];
                #pragma unroll
                for (int half = 0; half < 2; half++) {
                    int rr = r0 + half * 8;
                    float v0 = acc[i][j][2 * half + 0] + bb0;
                    float v1 = acc[i][j][2 * half + 1] + bb1;
                    __half h0 = __float2half_rn(gelu_erf(v0));
                    __half h1 = __float2half_rn(gelu_erf(v1));
                    uint32_t ph = ((uint32_t)__half_as_ushort(h1) << 16) | __half_as_ushort(h0);
                    *reinterpret_cast<uint32_t*>(&g_h[((size_t)e * MAX_T + rr) * F + fc + fl]) = ph;
                }
            }
        }
#endif
        __threadfence();
        __syncthreads();
        if (tid == 0) ctr_release(&g_cH[t * E + e]);
        return;
    }
    b -= nb1;

    // ================= GEMM2 consumer =================
    {
        const int t = b >> 6;
        const int e = (b >> 2) & 15;
        const int hh0 = (b & 3) * 128;
        const int tok0 = t * 128;

        if (tid == 0) ctr_wait_consume(&g_cH[t * E + e], 8u, 4u);
        __syncthreads();
        __threadfence();

        const __half* A = g_h + ((size_t)e * MAX_T + tok0) * F;
        const __half* B = g_w2t + ((size_t)e * H + hh0) * F;

#if USE_TC
        uint32_t tmem = tc_prologue(su, tid, wid);
        tc_mainloop(su, tmem, A, F, B, F, F, tid, wid);
        const int row = (wid & 3) * 32 + lane;
        const int ch = (wid >> 2) * 64;
        float* orow = out + (((size_t)(tok0 + row)) * E + e) * H;
        for (int cb = 0; cb < 64; cb += 32) {
            uint32_t r[32];
            TCGEN05_LD_X32(r, tmem + ch + cb);
            TCGEN05_WAIT_LD();
            int hglob = hh0 + ch + cb;
            float v4[4];
            #pragma unroll
            for (int j = 0; j < 32; j++) {
                v4[j & 3] = __uint_as_float(r[j]) + b2[e * H + hglob + j];
                if ((j & 3) == 3)
                    *reinterpret_cast<uint4*>(orow + hglob + (j & ~3)) =
                        *reinterpret_cast<uint4*>(v4);
            }
        }
        tc_release_tm(su, tmem, tid, wid);
#else
        float acc[2][8][4];
        #pragma unroll
        for (int i = 0; i < 2; i++)
            #pragma unroll
            for (int j = 0; j < 8; j++)
                #pragma unroll
                for (int q = 0; q < 4; q++) acc[i][j][q] = 0.0f;

        mmasync_mainloop(su, A, F, B, F, F, tid, acc);

        const int wm = wid >> 1, wn = wid & 1;
        const float* b2p = b2 + e * H;
        #pragma unroll
        for (int i = 0; i < 2; i++) {
            #pragma unroll
            for (int j = 0; j < 8; j++) {
                int hj = hh0 + wn * 64 + j * 8 + (lane & 3) * 2;
                int r0 = tok0 + wm * 32 + i * 16 + (lane >> 2);
                float bb0 = b2p[hj], bb1 = b2p[hj + 1];
                #pragma unroll
                for (int half = 0; half < 2; half++) {
                    int rr = r0 + half * 8;
                    float2 v = make_float2(acc[i][j][2 * half + 0] + bb0,
                                           acc[i][j][2 * half + 1] + bb1);
                    *reinterpret_cast<float2*>(out + ((size_t)rr * E + e) * H + hj) = v;
                }
            }
        }
#endif
    }
}

// ---------------------------------------------------------------------------
extern "C" void kernel_launch(void* const* d_in, const int* in_sizes, int n_in,
                              void* d_out, int out_size)
{
    const float* tokens = (const float*)d_in[0];
    const float* ln_g   = (const float*)d_in[1];
    const float* ln_b   = (const float*)d_in[2];
    const float* W1     = (const float*)d_in[3];
    const float* b1     = (const float*)d_in[4];
    const float* W2     = (const float*)d_in[5];
    const float* b2     = (const float*)d_in[6];
    float* out = (float*)d_out;

    int T = in_sizes[0] / H;      // 8192
    int tiles = T / 128;          // 64
    int nbLN = T / 8;             // 1024

    cudaFuncSetAttribute(gemm_fused_kernel, cudaFuncAttributeMaxDynamicSharedMemorySize, SMEM_BYTES);

    prep_kernel<<<nbLN + 4096, 256>>>(tokens, ln_g, ln_b, W1, W2, nbLN);

    int ng = tiles * E * 8 + tiles * E * 4;   // 12288
    gemm_fused_kernel<<<ng, 256, SMEM_BYTES>>>(b1, b2, out, tiles);
}

// round 17
// speedup vs baseline: 1.1261x; 1.0090x over previous
#include <cuda_runtime.h>
#include <cuda_fp16.h>
#include <math.h>
#include <stdint.h>

#define H 512
#define F 1024
#define E 16
#define MAX_T 8192
#define EPS 1e-5f

// Per-compile-pass feature detection: tcgen05 only legal on sm_103a-style targets.
#if defined(__CUDA_ARCH__) && (defined(__CUDA_ARCH_FEAT_SM103_ALL) || \
    defined(__CUDA_ARCH_FEAT_SM100_ALL) || defined(__CUDA_ARCH_SPECIFIC__) || \
    defined(__CUDA_ARCH_FAMILY_SPECIFIC__))
#define USE_TC 1
#else
#define USE_TC 0
#endif

// ---------------------------------------------------------------------------
// Scratch (no allocation allowed -> device globals)
// ---------------------------------------------------------------------------
__device__ __align__(128) __half g_x[(size_t)MAX_T * H];
__device__ __align__(128) __half g_w1t[(size_t)E * F * H];   // [e][f][h]
__device__ __align__(128) __half g_w2t[(size_t)E * H * F];   // [e][h][f]
__device__ float g_b1part[8][E * F];
__device__ __align__(128) __half g_h[(size_t)E * MAX_T * F]; // [e][t][f]

// Self-resetting counter (proven R10-R16): low16 = producers, high16 = consumers;
// last consumer zeroes the word. Zero-init at load; invariant across replays.
__device__ unsigned g_cH[(MAX_T / 128) * E];   // prod 8, cons 4

// ---------------------------------------------------------------------------
// Common helpers
// ---------------------------------------------------------------------------
__device__ __forceinline__ uint32_t smem_to_u32(const void* p) {
    uint32_t a;
    asm("{ .reg .u64 t; cvta.to.shared.u64 t, %1; cvt.u32.u64 %0, t; }" : "=r"(a) : "l"(p));
    return a;
}
#define SMEM_SWIZZLE_128B(o) ((o) ^ (((o) >> 3) & 0x70))

__device__ __forceinline__ void cpa16(uint32_t dst, const void* src) {
    asm volatile("cp.async.cg.shared.global [%0], [%1], 16;" :: "r"(dst), "l"(src));
}
#define CP_COMMIT() asm volatile("cp.async.commit_group;" ::: "memory")
__device__ __forceinline__ void cp_wait1() { asm volatile("cp.async.wait_group 1;" ::: "memory"); }
__device__ __forceinline__ void cp_wait0() { asm volatile("cp.async.wait_group 0;" ::: "memory"); }

__device__ __forceinline__ float gelu_erf(float x) {
    return 0.5f * x * (1.0f + erff(x * 0.70710678118654752f));
}

// Counter ops
__device__ __forceinline__ void ctr_release(unsigned* c) {
    asm volatile("red.release.gpu.global.add.u32 [%0], 1;" :: "l"(c) : "memory");
}
__device__ __forceinline__ unsigned ld_acq(const unsigned* c) {
    unsigned v;
    asm volatile("ld.acquire.gpu.global.u32 %0, [%1];" : "=r"(v) : "l"(c) : "memory");
    return v;
}
__device__ __forceinline__ void ctr_wait_consume(unsigned* c, unsigned target, unsigned ncons) {
    unsigned v;
    do {
        v = ld_acq(c);
        if ((v & 0xFFFFu) >= target) break;
        __nanosleep(256);
    } while (true);
    unsigned old = atomicAdd(c, 1u << 16);
    if ((old >> 16) == ncons - 1) atomicExch(c, 0u);
}

// Tile geometry: M=128 tokens, N=128, K-step=64
// SMEM stage: A(16K) B(16K) = 32KB; 2 stages = 64KB; 3 CTAs/SM
#define OFF_B 16384
#define STAGE_BYTES 32768
#define S_CTRL 65536             // tmem ptr (tc path)
#define S_MBAR 65552
#define S_B1   65568             // 128 floats of b1' for this fc tile
#define SMEM_BYTES 66080

// Full-stage load (A + B halves)
__device__ __forceinline__ void stage_load_async(uint32_t sbase,
    const __half* __restrict__ A, size_t as,
    const __half* __restrict__ B, size_t bs,
    int k0, int tid)
{
    #pragma unroll
    for (int it = 0; it < 4; it++) {
        int v = tid + it * 256;
        int r = v >> 3, c = v & 7;
        uint32_t off = SMEM_SWIZZLE_128B((uint32_t)(r * 128 + c * 16));
        cpa16(sbase + off,         A + (size_t)r * as + k0 + c * 8);
        cpa16(sbase + OFF_B + off, B + (size_t)r * bs + k0 + c * 8);
    }
}

// ===========================================================================
#if USE_TC
// tcgen05 path: one M=128 x N=128 MMA region (2-stage pipeline)
// ===========================================================================
__device__ __forceinline__ uint32_t elect_one_pred() {
    uint32_t pred;
    asm volatile("{\n\t.reg .pred p;\n\telect.sync _|p, 0xFFFFFFFF;\n\t"
                 "selp.b32 %0, 1, 0, p;\n\t}" : "=r"(pred));
    return pred;
}
static constexpr uint64_t SMEM_DESC_BASE_SW128 =
    (uint64_t(2) << 61) | (uint64_t(1) << 46) | (uint64_t(64) << 32) | (uint64_t(1) << 16);
#define MAKE_SMEM_DESC(a) (SMEM_DESC_BASE_SW128 | ((uint64_t)((a) >> 4) & 0x3FFF))

#define TCGEN05_ALLOC(sr, n) \
    asm volatile("tcgen05.alloc.cta_group::1.sync.aligned.shared::cta.b32 [%0], %1;" \
                 :: "r"((uint32_t)(sr)), "r"((uint32_t)(n)) : "memory")
#define TCGEN05_DEALLOC(t, n) \
    asm volatile("tcgen05.dealloc.cta_group::1.sync.aligned.b32 %0, %1;" :: "r"(t), "r"(n))
#define TCGEN05_RELINQUISH() \
    asm volatile("tcgen05.relinquish_alloc_permit.cta_group::1.sync.aligned;")
#define TCGEN05_COMMIT(m) \
    asm volatile("tcgen05.commit.cta_group::1.mbarrier::arrive::one.shared::cluster.b64 [%0];" \
                 :: "r"((uint32_t)(m)) : "memory")
#define TCGEN05_FENCE_AFTER() asm volatile("tcgen05.fence::after_thread_sync;" ::: "memory")
#define TCGEN05_WAIT_LD() asm volatile("tcgen05.wait::ld.sync.aligned;" ::: "memory")
#define MBARRIER_INIT(m, c) \
    asm volatile("mbarrier.init.shared.b64 [%0], %1;" :: "r"((uint32_t)(m)), "r"((uint32_t)(c)) : "memory")
#define MBARRIER_INVAL(m) \
    asm volatile("mbarrier.inval.shared.b64 [%0];" :: "r"((uint32_t)(m)) : "memory")

#define MBARRIER_WAIT_PARITY(mb, ph) do {                                         \
    uint32_t _m = (uint32_t)(mb), _p = (uint32_t)(ph), _d;                         \
    asm volatile("{\n\t.reg .pred p;\n\t"                                          \
        "mbarrier.try_wait.parity.acquire.cta.shared::cta.b64 p, [%1], %2;\n\t"    \
        "selp.b32 %0, 1, 0, p;\n\t}" : "=r"(_d) : "r"(_m), "r"(_p) : "memory");    \
    if (!_d) {                                                                     \
        asm volatile("{\n\t.reg .pred P1;\n\t"                                     \
            "WL_%=:\n\t"                                                           \
            "mbarrier.try_wait.parity.acquire.cta.shared::cta.b64 P1, [%0], %1, 0x989680;\n\t" \
            "@P1 bra.uni WD_%=;\n\t"                                               \
            "bra.uni WL_%=;\n\t"                                                   \
            "WD_%=:\n\t}" :: "r"(_m), "r"(_p) : "memory");                         \
    }                                                                              \
} while (0)

#define TCGEN05_LD_X32(r, a)                                                       \
    asm volatile("tcgen05.ld.sync.aligned.32x32b.x32.b32 "                         \
        "{%0, %1, %2, %3, %4, %5, %6, %7, %8, %9, %10, %11, %12, %13, %14, %15, "  \
        " %16, %17, %18, %19, %20, %21, %22, %23, %24, %25, %26, %27, %28, %29, %30, %31}, [%32];" \
        : "=r"((r)[0]), "=r"((r)[1]), "=r"((r)[2]), "=r"((r)[3]),                  \
          "=r"((r)[4]), "=r"((r)[5]), "=r"((r)[6]), "=r"((r)[7]),                  \
          "=r"((r)[8]), "=r"((r)[9]), "=r"((r)[10]), "=r"((r)[11]),                \
          "=r"((r)[12]), "=r"((r)[13]), "=r"((r)[14]), "=r"((r)[15]),              \
          "=r"((r)[16]), "=r"((r)[17]), "=r"((r)[18]), "=r"((r)[19]),              \
          "=r"((r)[20]), "=r"((r)[21]), "=r"((r)[22]), "=r"((r)[23]),              \
          "=r"((r)[24]), "=r"((r)[25]), "=r"((r)[26]), "=r"((r)[27]),              \
          "=r"((r)[28]), "=r"((r)[29]), "=r"((r)[30]), "=r"((r)[31])               \
        : "r"(a))

__device__ __forceinline__ void mma_f16_ss(uint32_t d_tmem, uint64_t a_desc,
                                           uint64_t b_desc, uint32_t idesc, bool acc) {
    uint32_t en = acc ? 1u : 0u;
    asm volatile("{\n\t.reg .pred p;\n\tsetp.ne.u32 p, %4, 0;\n\t"
                 "tcgen05.mma.cta_group::1.kind::f16 [%0], %1, %2, %3, p;\n\t}"
                 :: "r"(d_tmem), "l"(a_desc), "l"(b_desc), "r"(idesc), "r"(en)
                 : "memory");
}
#define MMA_IDESC ((1u << 4) | ((128u / 8u) << 17) | ((128u / 16u) << 24))

__device__ __forceinline__ uint32_t tc_prologue(uint32_t su, int tid, int wid) {
    if (wid == 0) TCGEN05_ALLOC(su + S_CTRL, 128);
    if (tid == 128) MBARRIER_INIT(su + S_MBAR, 1);
    __syncthreads();
    uint32_t tmem;
    asm volatile("ld.shared.b32 %0, [%1];" : "=r"(tmem) : "r"(su + S_CTRL));
    if (wid == 0) TCGEN05_RELINQUISH();
    __syncthreads();
    return tmem;
}

__device__ __forceinline__ void tc_mainloop(uint32_t su, uint32_t tmem,
    const __half* __restrict__ A, size_t as,
    const __half* __restrict__ B, size_t bs,
    int K, int tid, int wid)
{
    const int nk = K / 64;
    stage_load_async(su, A, as, B, bs, 0, tid);
    CP_COMMIT();
    #pragma unroll 2
    for (int ks = 0; ks < nk; ks++) {
        if (ks > 0) MBARRIER_WAIT_PARITY(su + S_MBAR, (ks - 1) & 1);
        if (ks + 1 < nk) {
            stage_load_async(su + ((ks + 1) & 1) * STAGE_BYTES,
                             A, as, B, bs, (ks + 1) * 64, tid);
            CP_COMMIT();
            cp_wait1();
        } else {
            cp_wait0();
        }
        __syncthreads();
        if (wid == 0 && elect_one_pred()) {
            asm volatile("fence.proxy.async.shared::cta;" ::: "memory");
            uint32_t sb = su + (ks & 1) * STAGE_BYTES;
            uint64_t dA = MAKE_SMEM_DESC(sb);
            uint64_t dB = MAKE_SMEM_DESC(sb + OFF_B);
            #pragma unroll
            for (int kk = 0; kk < 4; kk++) {
                bool acc0 = (ks > 0) || (kk > 0);
                mma_f16_ss(tmem, dA + kk * 2, dB + kk * 2, MMA_IDESC, acc0);
            }
            TCGEN05_COMMIT(su + S_MBAR);
        }
        __syncthreads();
    }
    MBARRIER_WAIT_PARITY(su + S_MBAR, (nk - 1) & 1);
    TCGEN05_FENCE_AFTER();
}

__device__ __forceinline__ void tc_release_tm(uint32_t su, uint32_t tmem, int tid, int wid) {
    __syncthreads();
    if (tid == 128) MBARRIER_INVAL(su + S_MBAR);
    __syncthreads();
    if (wid == 0) TCGEN05_DEALLOC(tmem, 128);
}
#endif  // USE_TC

// ===========================================================================
#if !USE_TC
// mma.sync fallback: 8 warps, warp tile 32x64, 2-stage pipeline
// ===========================================================================
__device__ __forceinline__ void ldsm_x4(uint32_t* r, uint32_t a) {
    asm volatile("ldmatrix.sync.aligned.m8n8.x4.shared.b16 {%0,%1,%2,%3}, [%4];"
                 : "=r"(r[0]), "=r"(r[1]), "=r"(r[2]), "=r"(r[3]) : "r"(a));
}
__device__ __forceinline__ void mma16816(float* d, const uint32_t* a, const uint32_t* b) {
    asm volatile("mma.sync.aligned.m16n8k16.row.col.f32.f16.f16.f32 "
                 "{%0,%1,%2,%3}, {%4,%5,%6,%7}, {%8,%9}, {%0,%1,%2,%3};"
                 : "+f"(d[0]), "+f"(d[1]), "+f"(d[2]), "+f"(d[3])
                 : "r"(a[0]), "r"(a[1]), "r"(a[2]), "r"(a[3]), "r"(b[0]), "r"(b[1]));
}

__device__ __forceinline__ void mmasync_mainloop(uint32_t su,
    const __half* __restrict__ A, size_t as,
    const __half* __restrict__ B, size_t bs,
    int K, int tid, float acc[2][8][4])
{
    const int nk = K / 64;
    const int wid = tid >> 5, lane = tid & 31;
    const int wm = wid >> 1, wn = wid & 1;

    // Precompute ks-invariant swizzled offsets (relative to stage base).
    uint32_t offB[4], offA[2];
    {
        int k = (lane >> 4) * 8;
        #pragma unroll
        for (int jj = 0; jj < 4; jj++) {
            int n = wn * 64 + jj * 16 + (lane & 7) + ((lane >> 3) & 1) * 8;
            offB[jj] = OFF_B + SMEM_SWIZZLE_128B((uint32_t)(n * 128 + k * 2));
        }
        #pragma unroll
        for (int i = 0; i < 2; i++) {
            int m = wm * 32 + i * 16 + (lane & 15);
            offA[i] = SMEM_SWIZZLE_128B((uint32_t)(m * 128 + k * 2));
        }
    }

    stage_load_async(su, A, as, B, bs, 0, tid);
    CP_COMMIT();

    #pragma unroll 2
    for (int ks = 0; ks < nk; ks++) {
        if (ks + 1 < nk) {
            stage_load_async(su + ((ks + 1) & 1) * STAGE_BYTES,
                             A, as, B, bs, (ks + 1) * 64, tid);
            CP_COMMIT();
            cp_wait1();
        } else {
            cp_wait0();
        }
        __syncthreads();

        uint32_t sA = su + (ks & 1) * STAGE_BYTES;

        #pragma unroll
        for (int k16 = 0; k16 < 64; k16 += 16) {
            // Adding k16*2 to the swizzled offset is exact: k*2 < 128 keeps
            // row bits constant and the swizzle mask depends only on row bits.
            uint32_t kadd = (uint32_t)(k16 * 2);
            uint32_t bh[8][2];
            #pragma unroll
            for (int jj = 0; jj < 4; jj++) {
                uint32_t t[4];
                ldsm_x4(t, sA + offB[jj] + kadd);
                bh[2 * jj][0] = t[0]; bh[2 * jj + 1][0] = t[1];
                bh[2 * jj][1] = t[2]; bh[2 * jj + 1][1] = t[3];
            }
            #pragma unroll
            for (int i = 0; i < 2; i++) {
                uint32_t ah[4];
                ldsm_x4(ah, sA + offA[i] + kadd);
                #pragma unroll
                for (int j = 0; j < 8; j++)
                    mma16816(acc[i][j], ah, bh[j]);
            }
        }
        __syncthreads();
    }
}
#endif  // !USE_TC

// ---------------------------------------------------------------------------
// Prep kernel (high occupancy, 16B-vectorized): LN + W1^T*g + b1 partials + W2^T
// ---------------------------------------------------------------------------
__global__ void __launch_bounds__(256) prep_kernel(
    const float* __restrict__ tokens, const float* __restrict__ ln_g,
    const float* __restrict__ ln_b,   const float* __restrict__ W1,
    const float* __restrict__ W2,     int nbLN)
{
    __shared__ float ts[64][65];
    __shared__ float ps[4][64];
    const int tid = threadIdx.x;
    int b = blockIdx.x;

    if (b < nbLN) {
        // ---- LN: warp per row, float4 loads, half2x2 stores ----
        const int wid = tid >> 5, lane = tid & 31;
        const int row = b * 8 + wid;
        const float4* x4 = reinterpret_cast<const float4*>(tokens + (size_t)row * H);
        float4 v[4];
        float s = 0.0f;
        #pragma unroll
        for (int i = 0; i < 4; i++) {
            v[i] = x4[lane + 32 * i];
            s += (v[i].x + v[i].y) + (v[i].z + v[i].w);
        }
        #pragma unroll
        for (int o = 16; o > 0; o >>= 1) s += __shfl_xor_sync(0xffffffffu, s, o);
        float mu = s * (1.0f / H);
        float q = 0.0f;
        #pragma unroll
        for (int i = 0; i < 4; i++) {
            v[i].x -= mu; v[i].y -= mu; v[i].z -= mu; v[i].w -= mu;
            q += (v[i].x * v[i].x + v[i].y * v[i].y) +
                 (v[i].z * v[i].z + v[i].w * v[i].w);
        }
        #pragma unroll
        for (int o = 16; o > 0; o >>= 1) q += __shfl_xor_sync(0xffffffffu, q, o);
        float rs = rsqrtf(q * (1.0f / H) + EPS);
        uint2* ox = reinterpret_cast<uint2*>(g_x + (size_t)row * H);
        #pragma unroll
        for (int i = 0; i < 4; i++) {
            __half h0 = __float2half_rn(v[i].x * rs);
            __half h1 = __float2half_rn(v[i].y * rs);
            __half h2 = __float2half_rn(v[i].z * rs);
            __half h3 = __float2half_rn(v[i].w * rs);
            uint2 p;
            p.x = ((uint32_t)__half_as_ushort(h1) << 16) | __half_as_ushort(h0);
            p.y = ((uint32_t)__half_as_ushort(h3) << 16) | __half_as_ushort(h2);
            ox[lane + 32 * i] = p;
        }
        return;
    }
    b -= nbLN;

    if (b < 2048) {
        // ---- W1^T * g + b1 partials (float4 loads, uint4 stores) ----
        int f0 = (b & 15) * 64, h0 = ((b >> 4) & 7) * 64, e = b >> 7;
        #pragma unroll
        for (int i = 0; i < 4; i++) {
            int idx = tid + i * 256;          // [0,1024): 64 rows x 16 float4
            int r = idx >> 4, c4 = (idx & 15) * 4;
            float4 w = *reinterpret_cast<const float4*>(
                &W1[((size_t)e * H + h0 + r) * F + f0 + c4]);
            ts[r][c4 + 0] = w.x; ts[r][c4 + 1] = w.y;
            ts[r][c4 + 2] = w.z; ts[r][c4 + 3] = w.w;
        }
        __syncthreads();
        #pragma unroll
        for (int i = 0; i < 2; i++) {
            int idx = tid + i * 256;          // [0,512): 64 f-rows x 8 uint4
            int r = idx >> 3, c8 = (idx & 7) * 8;
            uint32_t p[4];
            #pragma unroll
            for (int j = 0; j < 4; j++) {
                float w0 = ts[c8 + 2 * j][r]     * ln_g[e * H + h0 + c8 + 2 * j];
                float w1 = ts[c8 + 2 * j + 1][r] * ln_g[e * H + h0 + c8 + 2 * j + 1];
                p[j] = ((uint32_t)__half_as_ushort(__float2half_rn(w1)) << 16) |
                       __half_as_ushort(__float2half_rn(w0));
            }
            *reinterpret_cast<uint4*>(&g_w1t[((size_t)e * F + f0 + r) * H + h0 + c8]) =
                make_uint4(p[0], p[1], p[2], p[3]);
        }
        {
            int f = tid & 63, q = tid >> 6;
            const float* lb = ln_b + e * H + h0 + q * 16;
            float s = 0.0f;
            #pragma unroll
            for (int r = 0; r < 16; r++) s += lb[r] * ts[q * 16 + r][f];
            ps[q][f] = s;
        }
        __syncthreads();
        if (tid < 64) {
            float a = ps[0][tid] + ps[1][tid] + ps[2][tid] + ps[3][tid];
            g_b1part[h0 >> 6][e * F + f0 + tid] = a;
        }
        return;
    }
    b -= 2048;

    // ---- W2^T (float4 loads, uint4 stores) ----
    {
        int h0 = (b & 7) * 64, f0 = ((b >> 3) & 15) * 64, e = b >> 7;
        #pragma unroll
        for (int i = 0; i < 4; i++) {
            int idx = tid + i * 256;
            int r = idx >> 4, c4 = (idx & 15) * 4;
            float4 w = *reinterpret_cast<const float4*>(
                &W2[((size_t)e * F + f0 + r) * H + h0 + c4]);
            ts[r][c4 + 0] = w.x; ts[r][c4 + 1] = w.y;
            ts[r][c4 + 2] = w.z; ts[r][c4 + 3] = w.w;
        }
        __syncthreads();
        #pragma unroll
        for (int i = 0; i < 2; i++) {
            int idx = tid + i * 256;
            int r = idx >> 3, c8 = (idx & 7) * 8;   // r = h index, c8 = f offset
            uint32_t p[4];
            #pragma unroll
            for (int j = 0; j < 4; j++) {
                float w0 = ts[c8 + 2 * j][r];
                float w1 = ts[c8 + 2 * j + 1][r];
                p[j] = ((uint32_t)__half_as_ushort(__float2half_rn(w1)) << 16) |
                       __half_as_ushort(__float2half_rn(w0));
            }
            *reinterpret_cast<uint4*>(&g_w2t[((size_t)e * H + h0 + r) * F + f0 + c8]) =
                make_uint4(p[0], p[1], p[2], p[3]);
        }
    }
}

// ---------------------------------------------------------------------------
// Fused GEMM kernel: [GEMM1 nb1][GEMM2 nb2], 3 CTAs/SM, 2-stage pipeline
// ---------------------------------------------------------------------------
__global__ void __launch_bounds__(256, 3) gemm_fused_kernel(
    const float* __restrict__ b1, const float* __restrict__ b2,
    float* __restrict__ out, int tiles)
{
    extern __shared__ char smem[];
    uint32_t su = smem_to_u32(smem);
    const int tid = threadIdx.x, wid = tid >> 5, lane = tid & 31;
    const int nb1 = tiles * E * 8;
    int b = blockIdx.x;

    if (b < nb1) {
        // ================= GEMM1 producer =================
        const int t = b >> 7;
        const int e = (b >> 3) & 15;
        const int fc = (b & 7) * 128;
        const int tok0 = t * 128;
        float* sm_b1 = reinterpret_cast<float*>(smem + S_B1);

        if (tid < 128) {
            int fg = e * F + fc + tid;
            float a = b1[fg];
            #pragma unroll
            for (int s = 0; s < 8; s++) a += g_b1part[s][fg];
            sm_b1[tid] = a;
        }

        const __half* A = g_x + (size_t)tok0 * H;
        const __half* B = g_w1t + ((size_t)e * F + fc) * H;

#if USE_TC
        uint32_t tmem = tc_prologue(su, tid, wid);
        tc_mainloop(su, tmem, A, H, B, H, H, tid, wid);
        const int row = (wid & 3) * 32 + lane;
        const int ch = (wid >> 2) * 64;
        const size_t hrow = ((size_t)e * MAX_T + tok0 + row) * F;
        for (int cb = 0; cb < 64; cb += 32) {
            uint32_t r[32];
            TCGEN05_LD_X32(r, tmem + ch + cb);
            TCGEN05_WAIT_LD();
            int fglob = fc + ch + cb;
            __half h8[8];
            #pragma unroll
            for (int j = 0; j < 32; j++) {
                float v = __uint_as_float(r[j]) + sm_b1[ch + cb + j];
                h8[j & 7] = __float2half_rn(gelu_erf(v));
                if ((j & 7) == 7)
                    *reinterpret_cast<uint4*>(&g_h[hrow + fglob + (j & ~7)]) =
                        *reinterpret_cast<uint4*>(h8);
            }
        }
        tc_release_tm(su, tmem, tid, wid);
#else
        float acc[2][8][4];
        #pragma unroll
        for (int i = 0; i < 2; i++)
            #pragma unroll
            for (int j = 0; j < 8; j++)
                #pragma unroll
                for (int q = 0; q < 4; q++) acc[i][j][q] = 0.0f;

        mmasync_mainloop(su, A, H, B, H, H, tid, acc);

        const int wm = wid >> 1, wn = wid & 1;
        #pragma unroll
        for (int i = 0; i < 2; i++) {
            #pragma unroll
            for (int j = 0; j < 8; j++) {
                int fl = wn * 64 + j * 8 + (lane & 3) * 2;
                int r0 = tok0 + wm * 32 + i * 16 + (lane >> 2);
                float bb0 = sm_b1[fl], bb1 = sm_b1[fl + 1];
                #pragma unroll
                for (int half = 0; half < 2; half++) {
                    int rr = r0 + half * 8;
                    float v0 = acc[i][j][2 * half + 0] + bb0;
                    float v1 = acc[i][j][2 * half + 1] + bb1;
                    __half h0 = __float2half_rn(gelu_erf(v0));
                    __half h1 = __float2half_rn(gelu_erf(v1));
                    uint32_t ph = ((uint32_t)__half_as_ushort(h1) << 16) | __half_as_ushort(h0);
                    *reinterpret_cast<uint32_t*>(&g_h[((size_t)e * MAX_T + rr) * F + fc + fl]) = ph;
                }
            }
        }
#endif
        __threadfence();
        __syncthreads();
        if (tid == 0) ctr_release(&g_cH[t * E + e]);
        return;
    }
    b -= nb1;

    // ================= GEMM2 consumer =================
    {
        const int t = b >> 6;
        const int e = (b >> 2) & 15;
        const int hh0 = (b & 3) * 128;
        const int tok0 = t * 128;

        if (tid == 0) ctr_wait_consume(&g_cH[t * E + e], 8u, 4u);
        __syncthreads();
        __threadfence();

        const __half* A = g_h + ((size_t)e * MAX_T + tok0) * F;
        const __half* B = g_w2t + ((size_t)e * H + hh0) * F;

#if USE_TC
        uint32_t tmem = tc_prologue(su, tid, wid);
        tc_mainloop(su, tmem, A, F, B, F, F, tid, wid);
        const int row = (wid & 3) * 32 + lane;
        const int ch = (wid >> 2) * 64;
        float* orow = out + (((size_t)(tok0 + row)) * E + e) * H;
        for (int cb = 0; cb < 64; cb += 32) {
            uint32_t r[32];
            TCGEN05_LD_X32(r, tmem + ch + cb);
            TCGEN05_WAIT_LD();
            int hglob = hh0 + ch + cb;
            float v4[4];
            #pragma unroll
            for (int j = 0; j < 32; j++) {
                v4[j & 3] = __uint_as_float(r[j]) + b2[e * H + hglob + j];
                if ((j & 3) == 3)
                    *reinterpret_cast<uint4*>(orow + hglob + (j & ~3)) =
                        *reinterpret_cast<uint4*>(v4);
            }
        }
        tc_release_tm(su, tmem, tid, wid);
#else
        float acc[2][8][4];
        #pragma unroll
        for (int i = 0; i < 2; i++)
            #pragma unroll
            for (int j = 0; j < 8; j++)
                #pragma unroll
                for (int q = 0; q < 4; q++) acc[i][j][q] = 0.0f;

        mmasync_mainloop(su, A, F, B, F, F, tid, acc);

        const int wm = wid >> 1, wn = wid & 1;
        const float* b2p = b2 + e * H;
        #pragma unroll
        for (int i = 0; i < 2; i++) {
            #pragma unroll
            for (int j = 0; j < 8; j++) {
                int hj = hh0 + wn * 64 + j * 8 + (lane & 3) * 2;
                int r0 = tok0 + wm * 32 + i * 16 + (lane >> 2);
                float bb0 = b2p[hj], bb1 = b2p[hj + 1];
                #pragma unroll
                for (int half = 0; half < 2; half++) {
                    int rr = r0 + half * 8;
                    float2 v = make_float2(acc[i][j][2 * half + 0] + bb0,
                                           acc[i][j][2 * half + 1] + bb1);
                    *reinterpret_cast<float2*>(out + ((size_t)rr * E + e) * H + hj) = v;
                }
            }
        }
#endif
    }
}

// ---------------------------------------------------------------------------
extern "C" void kernel_launch(void* const* d_in, const int* in_sizes, int n_in,
                              void* d_out, int out_size)
{
    const float* tokens = (const float*)d_in[0];
    const float* ln_g   = (const float*)d_in[1];
    const float* ln_b   = (const float*)d_in[2];
    const float* W1     = (const float*)d_in[3];
    const float* b1     = (const float*)d_in[4];
    const float* W2     = (const float*)d_in[5];
    const float* b2     = (const float*)d_in[6];
    float* out = (float*)d_out;

    int T = in_sizes[0] / H;      // 8192
    int tiles = T / 128;          // 64
    int nbLN = T / 8;             // 1024

    cudaFuncSetAttribute(gemm_fused_kernel, cudaFuncAttributeMaxDynamicSharedMemorySize, SMEM_BYTES);

    prep_kernel<<<nbLN + 4096, 256>>>(tokens, ln_g, ln_b, W1, W2, nbLN);

    int ng = tiles * E * 8 + tiles * E * 4;   // 12288
    gemm_fused_kernel<<<ng, 256, SMEM_BYTES>>>(b1, b2, out, tiles);
}